// round 1
// baseline (speedup 1.0000x reference)
#include <cuda_runtime.h>
#include <math.h>

#define NB 8
#define NT 1221
#define NC 1024
#define NH 16
#define ND 64
#define NM (NB*NT)      // 9768
#define HV 6            // int(16*0.4)
#define VTS 12          // HV + int(16*0.4)

// ---------------- scratch (device globals; no allocation allowed) ------------
__device__ float g_q[NB*NH*NT*ND];   // [B,H,T,D]
__device__ float g_k[NB*NH*NT*ND];
__device__ float g_v[NB*NH*NT*ND];
__device__ float g_ao[NM*NC];        // attention out, [B*T, H*D]
__device__ float g_cs[NT*32];        // rope cos [T, D/2]
__device__ float g_sn[NT*32];        // rope sin

// ---------------- rope table -------------------------------------------------
__global__ void cis_kernel() {
    int idx = blockIdx.x*256 + threadIdx.x;
    if (idx >= NT*32) return;
    int t = idx >> 5;
    int i = idx & 31;
    float inv = powf(10000.0f, -((float)(2*i) / 64.0f));
    float ang = (float)t * inv;
    float s, c;
    sincosf(ang, &s, &c);
    g_cs[idx] = c;
    g_sn[idx] = s;
}

// ---------------- fused QKV GEMM + RoPE + head transpose ---------------------
// out = X @ W^T ; X [NM, NC] row-major, W [NC, NC] row-major (out-dim major)
// blockIdx.z: 0 -> Q (rope), 1 -> K (rope), 2 -> V
__global__ __launch_bounds__(256) void qkv_kernel(
    const float* __restrict__ X,
    const float* __restrict__ Wq,
    const float* __restrict__ Wk,
    const float* __restrict__ Wv)
{
    __shared__ float sA[16][128];   // [k][m]
    __shared__ float sB[16][128];   // [k][n]
    const int which = blockIdx.z;
    const float* __restrict__ W = (which==0) ? Wq : ((which==1) ? Wk : Wv);
    float* __restrict__ dst = (which==0) ? g_q : ((which==1) ? g_k : g_v);

    const int m0 = blockIdx.x * 128;
    const int n0 = blockIdx.y * 128;
    const int tid = threadIdx.x;
    const int tr = tid >> 4;       // 0..15 -> 8 rows each
    const int tc = tid & 15;       // 0..15 -> 8 cols each
    const int lrow = tid >> 1;     // 0..127
    const int lk   = (tid & 1) * 8;

    float acc[8][8];
    #pragma unroll
    for (int i = 0; i < 8; i++)
        #pragma unroll
        for (int j = 0; j < 8; j++) acc[i][j] = 0.f;

    for (int k0 = 0; k0 < NC; k0 += 16) {
        float4 a0, a1, b0, b1;
        int gm = m0 + lrow;
        if (gm < NM) {
            a0 = *(const float4*)&X[(size_t)gm*NC + k0 + lk];
            a1 = *(const float4*)&X[(size_t)gm*NC + k0 + lk + 4];
        } else {
            a0 = make_float4(0.f,0.f,0.f,0.f); a1 = a0;
        }
        b0 = *(const float4*)&W[(size_t)(n0+lrow)*NC + k0 + lk];
        b1 = *(const float4*)&W[(size_t)(n0+lrow)*NC + k0 + lk + 4];
        __syncthreads();
        sA[lk+0][lrow]=a0.x; sA[lk+1][lrow]=a0.y; sA[lk+2][lrow]=a0.z; sA[lk+3][lrow]=a0.w;
        sA[lk+4][lrow]=a1.x; sA[lk+5][lrow]=a1.y; sA[lk+6][lrow]=a1.z; sA[lk+7][lrow]=a1.w;
        sB[lk+0][lrow]=b0.x; sB[lk+1][lrow]=b0.y; sB[lk+2][lrow]=b0.z; sB[lk+3][lrow]=b0.w;
        sB[lk+4][lrow]=b1.x; sB[lk+5][lrow]=b1.y; sB[lk+6][lrow]=b1.z; sB[lk+7][lrow]=b1.w;
        __syncthreads();
        #pragma unroll
        for (int kk = 0; kk < 16; kk++) {
            float a[8], b[8];
            *(float4*)&a[0] = *(const float4*)&sA[kk][tr*8];
            *(float4*)&a[4] = *(const float4*)&sA[kk][tr*8+4];
            *(float4*)&b[0] = *(const float4*)&sB[kk][tc*8];
            *(float4*)&b[4] = *(const float4*)&sB[kk][tc*8+4];
            #pragma unroll
            for (int i = 0; i < 8; i++)
                #pragma unroll
                for (int j = 0; j < 8; j++)
                    acc[i][j] += a[i]*b[j];
        }
    }

    // epilogue: rope (Q,K) + scatter to [B,H,T,D]
    #pragma unroll
    for (int i = 0; i < 8; i++) {
        int gm = m0 + tr*8 + i;
        if (gm >= NM) continue;
        int bb = gm / NT;
        int t  = gm - bb*NT;
        #pragma unroll
        for (int j = 0; j < 8; j += 2) {
            int n = n0 + tc*8 + j;
            int h = n >> 6, d = n & 63;
            float e = acc[i][j], o = acc[i][j+1];
            float oe, oo;
            if (which < 2) {
                float cv = g_cs[t*32 + (d>>1)];
                float sv = g_sn[t*32 + (d>>1)];
                oe = e*cv - o*sv;
                oo = e*sv + o*cv;
            } else { oe = e; oo = o; }
            float2* p = (float2*)&dst[((size_t)((bb*NH + h)*NT) + t)*ND + d];
            *p = make_float2(oe, oo);
        }
    }
}

// ---------------- attention: flash-style with modality mask ------------------
// block: 64 q rows x full D=64; 256 threads (16x16, 4x4 per thread)
#define SMEM_FLOATS (3*64*68 + 64*64)

__global__ __launch_bounds__(256) void attn_kernel(const int* __restrict__ svp)
{
    extern __shared__ float sm[];
    float* sQt = sm;                 // [d][r], pitch 68
    float* sKt = sm + 64*68;         // [d][c], pitch 68
    float* sP  = sm + 2*64*68;       // [r][c], pitch 68
    float* sV  = sm + 3*64*68;       // [kv][dv], pitch 64

    const int S_V = *svp;
    const int qt = blockIdx.x, h = blockIdx.y, b = blockIdx.z;
    const int q0 = qt * 64;
    const int tid = threadIdx.x;
    const int tr = tid >> 4;   // 0..15 -> rows tr*4..tr*4+3
    const int tc = tid & 15;   // 0..15 -> cols tc*4..tc*4+3

    const size_t base = (size_t)((b*NH + h)*NT) * ND;
    const float* __restrict__ Qb = g_q + base;
    const float* __restrict__ Kb = g_k + base;
    const float* __restrict__ Vb = g_v + base;

    // load Q tile transposed
    #pragma unroll
    for (int it = 0; it < 16; it++) {
        int idx = it*256 + tid;
        int r = idx >> 6, d = idx & 63;
        int q = q0 + r;
        sQt[d*68 + r] = (q < NT) ? Qb[(size_t)q*ND + d] : 0.f;
    }

    float m_i[4], l_i[4], o[4][4];
    #pragma unroll
    for (int i = 0; i < 4; i++) {
        m_i[i] = -1e30f; l_i[i] = 0.f;
        #pragma unroll
        for (int j = 0; j < 4; j++) o[i][j] = 0.f;
    }

    const int ceil_sv = (S_V + 63) >> 6;
    int kv_lo = 0, kv_hi = 0;
    if (h < HV) {
        if (q0 < S_V) { kv_lo = 0; kv_hi = ceil_sv; }
    } else if (h < VTS) {
        if (q0 + 63 >= S_V) { kv_lo = S_V >> 6; kv_hi = qt + 1; }
    } else {
        kv_lo = 0; kv_hi = (qt + 1 > ceil_sv) ? (qt + 1) : ceil_sv;
    }
    __syncthreads();

    for (int kvt = kv_lo; kvt < kv_hi; kvt++) {
        const int kv0 = kvt * 64;
        #pragma unroll
        for (int it = 0; it < 16; it++) {
            int idx = it*256 + tid;
            int c = idx >> 6, d = idx & 63;
            int kv = kv0 + c;
            float kx = (kv < NT) ? Kb[(size_t)kv*ND + d] : 0.f;
            float vx = (kv < NT) ? Vb[(size_t)kv*ND + d] : 0.f;
            sKt[d*68 + c] = kx;
            sV[c*64 + d]  = vx;
        }
        __syncthreads();

        float s[4][4];
        #pragma unroll
        for (int i = 0; i < 4; i++)
            #pragma unroll
            for (int j = 0; j < 4; j++) s[i][j] = 0.f;

        #pragma unroll 16
        for (int d = 0; d < 64; d++) {
            float4 a  = *(const float4*)&sQt[d*68 + tr*4];
            float4 bb = *(const float4*)&sKt[d*68 + tc*4];
            float av[4] = {a.x, a.y, a.z, a.w};
            float bv[4] = {bb.x, bb.y, bb.z, bb.w};
            #pragma unroll
            for (int i = 0; i < 4; i++)
                #pragma unroll
                for (int j = 0; j < 4; j++)
                    s[i][j] += av[i]*bv[j];
        }

        // mask + scale
        #pragma unroll
        for (int i = 0; i < 4; i++) {
            int q = q0 + tr*4 + i;
            #pragma unroll
            for (int j = 0; j < 4; j++) {
                int kv = kv0 + tc*4 + j;
                bool ok;
                if (h < HV)        ok = (q < S_V) && (kv < S_V);
                else if (h < VTS)  ok = (q >= S_V) && (kv >= S_V) && (q >= kv);
                else               ok = (kv < S_V) || (q >= kv);
                ok = ok && (kv < NT) && (q < NT);
                s[i][j] = ok ? s[i][j] * 0.125f : -1e30f;
            }
        }

        // online softmax update (row stats shared across the 16 tc lanes)
        #pragma unroll
        for (int i = 0; i < 4; i++) {
            float rm = fmaxf(fmaxf(s[i][0], s[i][1]), fmaxf(s[i][2], s[i][3]));
            rm = fmaxf(rm, __shfl_xor_sync(0xffffffffu, rm, 8));
            rm = fmaxf(rm, __shfl_xor_sync(0xffffffffu, rm, 4));
            rm = fmaxf(rm, __shfl_xor_sync(0xffffffffu, rm, 2));
            rm = fmaxf(rm, __shfl_xor_sync(0xffffffffu, rm, 1));
            float mnew = fmaxf(m_i[i], rm);
            float alpha = __expf(m_i[i] - mnew);
            m_i[i] = mnew;
            float psum = 0.f;
            #pragma unroll
            for (int j = 0; j < 4; j++) {
                float p = __expf(s[i][j] - mnew);
                s[i][j] = p;
                psum += p;
            }
            psum += __shfl_xor_sync(0xffffffffu, psum, 8);
            psum += __shfl_xor_sync(0xffffffffu, psum, 4);
            psum += __shfl_xor_sync(0xffffffffu, psum, 2);
            psum += __shfl_xor_sync(0xffffffffu, psum, 1);
            l_i[i] = l_i[i]*alpha + psum;
            #pragma unroll
            for (int j = 0; j < 4; j++) o[i][j] *= alpha;
        }

        // stage P, then O += P @ V
        #pragma unroll
        for (int i = 0; i < 4; i++)
            #pragma unroll
            for (int j = 0; j < 4; j++)
                sP[(tr*4+i)*68 + tc*4 + j] = s[i][j];
        __syncthreads();

        #pragma unroll 8
        for (int kv = 0; kv < 64; kv++) {
            float p0 = sP[(tr*4+0)*68 + kv];
            float p1 = sP[(tr*4+1)*68 + kv];
            float p2 = sP[(tr*4+2)*68 + kv];
            float p3 = sP[(tr*4+3)*68 + kv];
            float4 v4 = *(const float4*)&sV[kv*64 + tc*4];
            o[0][0] += p0*v4.x; o[0][1] += p0*v4.y; o[0][2] += p0*v4.z; o[0][3] += p0*v4.w;
            o[1][0] += p1*v4.x; o[1][1] += p1*v4.y; o[1][2] += p1*v4.z; o[1][3] += p1*v4.w;
            o[2][0] += p2*v4.x; o[2][1] += p2*v4.y; o[2][2] += p2*v4.z; o[2][3] += p2*v4.w;
            o[3][0] += p3*v4.x; o[3][1] += p3*v4.y; o[3][2] += p3*v4.z; o[3][3] += p3*v4.w;
        }
        __syncthreads();
    }

    // epilogue: normalize; fully-masked rows -> 0 (reference row_any semantics)
    float* __restrict__ Ob = g_ao + (size_t)(b*NT)*NC + h*ND;
    #pragma unroll
    for (int i = 0; i < 4; i++) {
        int q = q0 + tr*4 + i;
        if (q >= NT) continue;
        float invl = (m_i[i] > -5e29f) ? (1.f / l_i[i]) : 0.f;
        float4 r4 = make_float4(o[i][0]*invl, o[i][1]*invl, o[i][2]*invl, o[i][3]*invl);
        *(float4*)&Ob[(size_t)q*NC + tc*4] = r4;
    }
}

// ---------------- output projection: out = AO @ Wo^T + bo --------------------
__global__ __launch_bounds__(256) void proj_kernel(
    const float* __restrict__ W,
    const float* __restrict__ bias,
    float* __restrict__ out)
{
    __shared__ float sA[16][128];
    __shared__ float sB[16][128];
    const int m0 = blockIdx.x * 128;
    const int n0 = blockIdx.y * 128;
    const int tid = threadIdx.x;
    const int tr = tid >> 4;
    const int tc = tid & 15;
    const int lrow = tid >> 1;
    const int lk   = (tid & 1) * 8;

    float acc[8][8];
    #pragma unroll
    for (int i = 0; i < 8; i++)
        #pragma unroll
        for (int j = 0; j < 8; j++) acc[i][j] = 0.f;

    for (int k0 = 0; k0 < NC; k0 += 16) {
        float4 a0, a1, b0, b1;
        int gm = m0 + lrow;
        if (gm < NM) {
            a0 = *(const float4*)&g_ao[(size_t)gm*NC + k0 + lk];
            a1 = *(const float4*)&g_ao[(size_t)gm*NC + k0 + lk + 4];
        } else {
            a0 = make_float4(0.f,0.f,0.f,0.f); a1 = a0;
        }
        b0 = *(const float4*)&W[(size_t)(n0+lrow)*NC + k0 + lk];
        b1 = *(const float4*)&W[(size_t)(n0+lrow)*NC + k0 + lk + 4];
        __syncthreads();
        sA[lk+0][lrow]=a0.x; sA[lk+1][lrow]=a0.y; sA[lk+2][lrow]=a0.z; sA[lk+3][lrow]=a0.w;
        sA[lk+4][lrow]=a1.x; sA[lk+5][lrow]=a1.y; sA[lk+6][lrow]=a1.z; sA[lk+7][lrow]=a1.w;
        sB[lk+0][lrow]=b0.x; sB[lk+1][lrow]=b0.y; sB[lk+2][lrow]=b0.z; sB[lk+3][lrow]=b0.w;
        sB[lk+4][lrow]=b1.x; sB[lk+5][lrow]=b1.y; sB[lk+6][lrow]=b1.z; sB[lk+7][lrow]=b1.w;
        __syncthreads();
        #pragma unroll
        for (int kk = 0; kk < 16; kk++) {
            float a[8], b[8];
            *(float4*)&a[0] = *(const float4*)&sA[kk][tr*8];
            *(float4*)&a[4] = *(const float4*)&sA[kk][tr*8+4];
            *(float4*)&b[0] = *(const float4*)&sB[kk][tc*8];
            *(float4*)&b[4] = *(const float4*)&sB[kk][tc*8+4];
            #pragma unroll
            for (int i = 0; i < 8; i++)
                #pragma unroll
                for (int j = 0; j < 8; j++)
                    acc[i][j] += a[i]*b[j];
        }
    }

    float4 bb0 = *(const float4*)&bias[n0 + tc*8];
    float4 bb1 = *(const float4*)&bias[n0 + tc*8 + 4];
    #pragma unroll
    for (int i = 0; i < 8; i++) {
        int gm = m0 + tr*8 + i;
        if (gm >= NM) continue;
        float4 o0 = make_float4(acc[i][0]+bb0.x, acc[i][1]+bb0.y, acc[i][2]+bb0.z, acc[i][3]+bb0.w);
        float4 o1 = make_float4(acc[i][4]+bb1.x, acc[i][5]+bb1.y, acc[i][6]+bb1.z, acc[i][7]+bb1.w);
        *(float4*)&out[(size_t)gm*NC + n0 + tc*8]     = o0;
        *(float4*)&out[(size_t)gm*NC + n0 + tc*8 + 4] = o1;
    }
}

// ---------------- launch -----------------------------------------------------
extern "C" void kernel_launch(void* const* d_in, const int* in_sizes, int n_in,
                              void* d_out, int out_size) {
    const float* x  = (const float*)d_in[0];
    const float* Wq = (const float*)d_in[1];
    const float* Wk = (const float*)d_in[2];
    const float* Wv = (const float*)d_in[3];
    const float* Wo = (const float*)d_in[4];
    const float* bo = (const float*)d_in[5];
    const int*   sv = (const int*)d_in[6];
    float* out = (float*)d_out;

    const int smem_bytes = SMEM_FLOATS * (int)sizeof(float);
    cudaFuncSetAttribute((const void*)attn_kernel,
                         cudaFuncAttributeMaxDynamicSharedMemorySize, smem_bytes);

    cis_kernel<<<(NT*32 + 255)/256, 256>>>();
    qkv_kernel<<<dim3((NM + 127)/128, NC/128, 3), 256>>>(x, Wq, Wk, Wv);
    attn_kernel<<<dim3((NT + 63)/64, NH, NB), 256, smem_bytes>>>(sv);
    proj_kernel<<<dim3((NM + 127)/128, NC/128), 256>>>(Wo, bo, out);
}

// round 3
// speedup vs baseline: 1.1791x; 1.1791x over previous
#include <cuda_runtime.h>
#include <math.h>
#include <stdint.h>

#define NB 8
#define NT 1221
#define NC 1024
#define NH 16
#define ND 64
#define NM (NB*NT)      // 9768
#define HV 6            // int(16*0.4)
#define VTS 12          // HV + int(16*0.4)

#define PITCH 36        // smem row pitch (floats) -> conflict-free tf32 fragment lds
#define KTILE 32
#define NKT   (NC/KTILE)

// ---------------- scratch (device globals; no allocation allowed) ------------
__device__ float g_q[NB*NH*NT*ND];   // [B,H,T,D]
__device__ float g_k[NB*NH*NT*ND];
__device__ float g_v[NB*NH*NT*ND];
__device__ float g_ao[NM*NC];        // attention out, [B*T, H*D]
__device__ float g_cs[NT*32];        // rope cos [T, D/2]
__device__ float g_sn[NT*32];        // rope sin

// ---------------- small helpers ----------------------------------------------
__device__ __forceinline__ uint32_t f2tf32(float x) {
    uint32_t u;
    asm("cvt.rna.tf32.f32 %0, %1;" : "=r"(u) : "f"(x));
    return u;
}
__device__ __forceinline__ void split_tf32(float x, uint32_t& hi, uint32_t& lo) {
    hi = f2tf32(x);
    float r = x - __uint_as_float(hi);
    lo = f2tf32(r);
}
__device__ __forceinline__ void mma8(float* d,
                                     uint32_t a0, uint32_t a1, uint32_t a2, uint32_t a3,
                                     uint32_t b0, uint32_t b1) {
    asm volatile(
        "mma.sync.aligned.m16n8k8.row.col.f32.tf32.tf32.f32 "
        "{%0,%1,%2,%3},{%4,%5,%6,%7},{%8,%9},{%0,%1,%2,%3};\n"
        : "+f"(d[0]), "+f"(d[1]), "+f"(d[2]), "+f"(d[3])
        : "r"(a0), "r"(a1), "r"(a2), "r"(a3), "r"(b0), "r"(b1));
}
__device__ __forceinline__ void cpa16(float* dst, const float* src, bool pred) {
    uint32_t d = (uint32_t)__cvta_generic_to_shared(dst);
    int sz = pred ? 16 : 0;
    asm volatile("cp.async.cg.shared.global [%0], [%1], 16, %2;\n"
                 :: "r"(d), "l"(src), "r"(sz));
}
#define CP_COMMIT() asm volatile("cp.async.commit_group;\n")

// ---------------- rope table -------------------------------------------------
__global__ void cis_kernel() {
    int idx = blockIdx.x*256 + threadIdx.x;
    if (idx >= NT*32) return;
    int t = idx >> 5;
    int i = idx & 31;
    float inv = powf(10000.0f, -((float)(2*i) / 64.0f));
    float ang = (float)t * inv;
    float s, c;
    sincosf(ang, &s, &c);
    g_cs[idx] = c;
    g_sn[idx] = s;
}

// ---------------- shared 3xTF32 GEMM mainloop --------------------------------
// Computes acc = A[m0:m0+128, :] @ B[n0:n0+128, :]^T  (A row-major [*,NC],
// B row-major [*,NC], i.e. out = A @ B^T which matches X @ W^T).
// 128 threads, 4 warps in 2x2 grid, 64x64 warp tiles, m16n8k8 TF32 mma.
__device__ __forceinline__ void gemm_main(
    const float* __restrict__ A, const float* __restrict__ Bw,
    int m0, int n0, float* sA, float* sB, float acc[4][8][4])
{
    const int tid  = threadIdx.x;
    const int lane = tid & 31;
    const int warp = tid >> 5;
    const int wm = (warp >> 1) * 64;
    const int wn = (warp & 1) * 64;
    const int g = lane >> 2;   // 0..7
    const int t = lane & 3;    // 0..3

    const bool pa = (m0 + tid) < NM;
    const float* arow = A  + (size_t)(m0 + tid) * NC;
    const float* brow = Bw + (size_t)(n0 + tid) * NC;

    // prologue: stage 0
    {
        float* da = sA + tid*PITCH;
        float* db = sB + tid*PITCH;
        #pragma unroll
        for (int i = 0; i < 8; i++) cpa16(da + i*4, arow + i*4, pa);
        #pragma unroll
        for (int i = 0; i < 8; i++) cpa16(db + i*4, brow + i*4, true);
        CP_COMMIT();
    }

    for (int kt = 0; kt < NKT; kt++) {
        const int buf = kt & 1;
        if (kt + 1 < NKT) {
            const int k0n = (kt + 1) * KTILE;
            float* da = sA + (buf^1)*128*PITCH + tid*PITCH;
            float* db = sB + (buf^1)*128*PITCH + tid*PITCH;
            #pragma unroll
            for (int i = 0; i < 8; i++) cpa16(da + i*4, arow + k0n + i*4, pa);
            #pragma unroll
            for (int i = 0; i < 8; i++) cpa16(db + i*4, brow + k0n + i*4, true);
            CP_COMMIT();
            asm volatile("cp.async.wait_group 1;\n" ::: "memory");
        } else {
            asm volatile("cp.async.wait_group 0;\n" ::: "memory");
        }
        __syncthreads();

        const float* tA = sA + buf*128*PITCH;
        const float* tB = sB + buf*128*PITCH;

        #pragma unroll
        for (int ks = 0; ks < 4; ks++) {
            uint32_t ah[4][4], al[4][4], bh[8][2], bl[8][2];
            #pragma unroll
            for (int mi = 0; mi < 4; mi++) {
                const int r0 = wm + mi*16 + g;
                float x0 = tA[(r0    )*PITCH + ks*8 + t    ];
                float x1 = tA[(r0 + 8)*PITCH + ks*8 + t    ];
                float x2 = tA[(r0    )*PITCH + ks*8 + t + 4];
                float x3 = tA[(r0 + 8)*PITCH + ks*8 + t + 4];
                split_tf32(x0, ah[mi][0], al[mi][0]);
                split_tf32(x1, ah[mi][1], al[mi][1]);
                split_tf32(x2, ah[mi][2], al[mi][2]);
                split_tf32(x3, ah[mi][3], al[mi][3]);
            }
            #pragma unroll
            for (int ni = 0; ni < 8; ni++) {
                const int r = wn + ni*8 + g;
                float y0 = tB[r*PITCH + ks*8 + t    ];
                float y1 = tB[r*PITCH + ks*8 + t + 4];
                split_tf32(y0, bh[ni][0], bl[ni][0]);
                split_tf32(y1, bh[ni][1], bl[ni][1]);
            }
            #pragma unroll
            for (int mi = 0; mi < 4; mi++)
                #pragma unroll
                for (int ni = 0; ni < 8; ni++) {
                    float* d = acc[mi][ni];
                    mma8(d, ah[mi][0], ah[mi][1], ah[mi][2], ah[mi][3], bh[ni][0], bh[ni][1]);
                    mma8(d, al[mi][0], al[mi][1], al[mi][2], al[mi][3], bh[ni][0], bh[ni][1]);
                    mma8(d, ah[mi][0], ah[mi][1], ah[mi][2], ah[mi][3], bl[ni][0], bl[ni][1]);
                }
        }
        __syncthreads();
    }
}

// ---------------- fused QKV GEMM (tensor core) + RoPE + head transpose -------
__global__ __launch_bounds__(128) void qkv_kernel(
    const float* __restrict__ X,
    const float* __restrict__ Wq,
    const float* __restrict__ Wk,
    const float* __restrict__ Wv)
{
    extern __shared__ float sm[];
    float* sA = sm;
    float* sB = sm + 2*128*PITCH;

    const int which = blockIdx.z;
    const float* __restrict__ W = (which==0) ? Wq : ((which==1) ? Wk : Wv);
    float* __restrict__ dst = (which==0) ? g_q : ((which==1) ? g_k : g_v);

    const int m0 = blockIdx.x * 128;
    const int n0 = blockIdx.y * 128;

    float acc[4][8][4];
    #pragma unroll
    for (int mi = 0; mi < 4; mi++)
        #pragma unroll
        for (int ni = 0; ni < 8; ni++)
            #pragma unroll
            for (int j = 0; j < 4; j++) acc[mi][ni][j] = 0.f;

    gemm_main(X, W, m0, n0, sA, sB, acc);

    const int tid  = threadIdx.x;
    const int lane = tid & 31;
    const int warp = tid >> 5;
    const int wm = (warp >> 1) * 64;
    const int wn = (warp & 1) * 64;
    const int g = lane >> 2;
    const int t = lane & 3;

    #pragma unroll
    for (int mi = 0; mi < 4; mi++) {
        #pragma unroll
        for (int half = 0; half < 2; half++) {
            const int m = m0 + wm + mi*16 + g + half*8;
            if (m >= NM) continue;
            const int bb  = m / NT;
            const int tok = m - bb*NT;
            #pragma unroll
            for (int ni = 0; ni < 8; ni++) {
                const int n = n0 + wn + ni*8 + 2*t;
                const int h = n >> 6, d = n & 63;
                float e = acc[mi][ni][half*2 + 0];
                float o = acc[mi][ni][half*2 + 1];
                float oe, oo;
                if (which < 2) {
                    float cv = g_cs[tok*32 + (d >> 1)];
                    float sv = g_sn[tok*32 + (d >> 1)];
                    oe = e*cv - o*sv;
                    oo = e*sv + o*cv;
                } else { oe = e; oo = o; }
                float2* p = (float2*)&dst[((size_t)((bb*NH + h)*NT) + tok)*ND + d];
                *p = make_float2(oe, oo);
            }
        }
    }
}

// ---------------- output projection (tensor core): out = AO @ Wo^T + bo ------
__global__ __launch_bounds__(128) void proj_kernel(
    const float* __restrict__ W,
    const float* __restrict__ bias,
    float* __restrict__ out)
{
    extern __shared__ float sm[];
    float* sA = sm;
    float* sB = sm + 2*128*PITCH;

    const int m0 = blockIdx.x * 128;
    const int n0 = blockIdx.y * 128;

    float acc[4][8][4];
    #pragma unroll
    for (int mi = 0; mi < 4; mi++)
        #pragma unroll
        for (int ni = 0; ni < 8; ni++)
            #pragma unroll
            for (int j = 0; j < 4; j++) acc[mi][ni][j] = 0.f;

    gemm_main(g_ao, W, m0, n0, sA, sB, acc);

    const int tid  = threadIdx.x;
    const int lane = tid & 31;
    const int warp = tid >> 5;
    const int wm = (warp >> 1) * 64;
    const int wn = (warp & 1) * 64;
    const int g = lane >> 2;
    const int t = lane & 3;

    #pragma unroll
    for (int mi = 0; mi < 4; mi++) {
        #pragma unroll
        for (int half = 0; half < 2; half++) {
            const int m = m0 + wm + mi*16 + g + half*8;
            if (m >= NM) continue;
            #pragma unroll
            for (int ni = 0; ni < 8; ni++) {
                const int n = n0 + wn + ni*8 + 2*t;
                float b0 = bias[n], b1 = bias[n+1];
                float2 r = make_float2(acc[mi][ni][half*2 + 0] + b0,
                                       acc[mi][ni][half*2 + 1] + b1);
                *(float2*)&out[(size_t)m*NC + n] = r;
            }
        }
    }
}

// ---------------- attention: flash-style with modality mask ------------------
#define SMEM_FLOATS (3*64*68 + 64*64)

__global__ __launch_bounds__(256) void attn_kernel(const int* __restrict__ svp)
{
    extern __shared__ float smf[];
    float* sQt = smf;                 // [d][r], pitch 68
    float* sKt = smf + 64*68;         // [d][c], pitch 68
    float* sP  = smf + 2*64*68;       // [r][c], pitch 68
    float* sV  = smf + 3*64*68;       // [kv][dv], pitch 64

    const int S_V = *svp;
    const int qt = blockIdx.x, h = blockIdx.y, b = blockIdx.z;
    const int q0 = qt * 64;
    const int tid = threadIdx.x;
    const int tr = tid >> 4;
    const int tc = tid & 15;

    const size_t base = (size_t)((b*NH + h)*NT) * ND;
    const float* __restrict__ Qb = g_q + base;
    const float* __restrict__ Kb = g_k + base;
    const float* __restrict__ Vb = g_v + base;

    #pragma unroll
    for (int it = 0; it < 16; it++) {
        int idx = it*256 + tid;
        int r = idx >> 6, d = idx & 63;
        int q = q0 + r;
        sQt[d*68 + r] = (q < NT) ? Qb[(size_t)q*ND + d] : 0.f;
    }

    float m_i[4], l_i[4], o[4][4];
    #pragma unroll
    for (int i = 0; i < 4; i++) {
        m_i[i] = -1e30f; l_i[i] = 0.f;
        #pragma unroll
        for (int j = 0; j < 4; j++) o[i][j] = 0.f;
    }

    const int ceil_sv = (S_V + 63) >> 6;
    int kv_lo = 0, kv_hi = 0;
    if (h < HV) {
        if (q0 < S_V) { kv_lo = 0; kv_hi = ceil_sv; }
    } else if (h < VTS) {
        if (q0 + 63 >= S_V) { kv_lo = S_V >> 6; kv_hi = qt + 1; }
    } else {
        kv_lo = 0; kv_hi = (qt + 1 > ceil_sv) ? (qt + 1) : ceil_sv;
    }
    __syncthreads();

    for (int kvt = kv_lo; kvt < kv_hi; kvt++) {
        const int kv0 = kvt * 64;
        #pragma unroll
        for (int it = 0; it < 16; it++) {
            int idx = it*256 + tid;
            int c = idx >> 6, d = idx & 63;
            int kv = kv0 + c;
            float kx = (kv < NT) ? Kb[(size_t)kv*ND + d] : 0.f;
            float vx = (kv < NT) ? Vb[(size_t)kv*ND + d] : 0.f;
            sKt[d*68 + c] = kx;
            sV[c*64 + d]  = vx;
        }
        __syncthreads();

        float s[4][4];
        #pragma unroll
        for (int i = 0; i < 4; i++)
            #pragma unroll
            for (int j = 0; j < 4; j++) s[i][j] = 0.f;

        #pragma unroll 16
        for (int d = 0; d < 64; d++) {
            float4 a  = *(const float4*)&sQt[d*68 + tr*4];
            float4 bb = *(const float4*)&sKt[d*68 + tc*4];
            float av[4] = {a.x, a.y, a.z, a.w};
            float bv[4] = {bb.x, bb.y, bb.z, bb.w};
            #pragma unroll
            for (int i = 0; i < 4; i++)
                #pragma unroll
                for (int j = 0; j < 4; j++)
                    s[i][j] += av[i]*bv[j];
        }

        #pragma unroll
        for (int i = 0; i < 4; i++) {
            int q = q0 + tr*4 + i;
            #pragma unroll
            for (int j = 0; j < 4; j++) {
                int kv = kv0 + tc*4 + j;
                bool ok;
                if (h < HV)        ok = (q < S_V) && (kv < S_V);
                else if (h < VTS)  ok = (q >= S_V) && (kv >= S_V) && (q >= kv);
                else               ok = (kv < S_V) || (q >= kv);
                ok = ok && (kv < NT) && (q < NT);
                s[i][j] = ok ? s[i][j] * 0.125f : -1e30f;
            }
        }

        #pragma unroll
        for (int i = 0; i < 4; i++) {
            float rm = fmaxf(fmaxf(s[i][0], s[i][1]), fmaxf(s[i][2], s[i][3]));
            rm = fmaxf(rm, __shfl_xor_sync(0xffffffffu, rm, 8));
            rm = fmaxf(rm, __shfl_xor_sync(0xffffffffu, rm, 4));
            rm = fmaxf(rm, __shfl_xor_sync(0xffffffffu, rm, 2));
            rm = fmaxf(rm, __shfl_xor_sync(0xffffffffu, rm, 1));
            float mnew = fmaxf(m_i[i], rm);
            float alpha = __expf(m_i[i] - mnew);
            m_i[i] = mnew;
            float psum = 0.f;
            #pragma unroll
            for (int j = 0; j < 4; j++) {
                float p = __expf(s[i][j] - mnew);
                s[i][j] = p;
                psum += p;
            }
            psum += __shfl_xor_sync(0xffffffffu, psum, 8);
            psum += __shfl_xor_sync(0xffffffffu, psum, 4);
            psum += __shfl_xor_sync(0xffffffffu, psum, 2);
            psum += __shfl_xor_sync(0xffffffffu, psum, 1);
            l_i[i] = l_i[i]*alpha + psum;
            #pragma unroll
            for (int j = 0; j < 4; j++) o[i][j] *= alpha;
        }

        #pragma unroll
        for (int i = 0; i < 4; i++)
            #pragma unroll
            for (int j = 0; j < 4; j++)
                sP[(tr*4+i)*68 + tc*4 + j] = s[i][j];
        __syncthreads();

        #pragma unroll 8
        for (int kv = 0; kv < 64; kv++) {
            float p0 = sP[(tr*4+0)*68 + kv];
            float p1 = sP[(tr*4+1)*68 + kv];
            float p2 = sP[(tr*4+2)*68 + kv];
            float p3 = sP[(tr*4+3)*68 + kv];
            float4 v4 = *(const float4*)&sV[kv*64 + tc*4];
            o[0][0] += p0*v4.x; o[0][1] += p0*v4.y; o[0][2] += p0*v4.z; o[0][3] += p0*v4.w;
            o[1][0] += p1*v4.x; o[1][1] += p1*v4.y; o[1][2] += p1*v4.z; o[1][3] += p1*v4.w;
            o[2][0] += p2*v4.x; o[2][1] += p2*v4.y; o[2][2] += p2*v4.z; o[2][3] += p2*v4.w;
            o[3][0] += p3*v4.x; o[3][1] += p3*v4.y; o[3][2] += p3*v4.z; o[3][3] += p3*v4.w;
        }
        __syncthreads();
    }

    float* __restrict__ Ob = g_ao + (size_t)(b*NT)*NC + h*ND;
    #pragma unroll
    for (int i = 0; i < 4; i++) {
        int q = q0 + tr*4 + i;
        if (q >= NT) continue;
        float invl = (m_i[i] > -5e29f) ? (1.f / l_i[i]) : 0.f;
        float4 r4 = make_float4(o[i][0]*invl, o[i][1]*invl, o[i][2]*invl, o[i][3]*invl);
        *(float4*)&Ob[(size_t)q*NC + tc*4] = r4;
    }
}

// ---------------- launch -----------------------------------------------------
extern "C" void kernel_launch(void* const* d_in, const int* in_sizes, int n_in,
                              void* d_out, int out_size) {
    const float* x  = (const float*)d_in[0];
    const float* Wq = (const float*)d_in[1];
    const float* Wk = (const float*)d_in[2];
    const float* Wv = (const float*)d_in[3];
    const float* Wo = (const float*)d_in[4];
    const float* bo = (const float*)d_in[5];
    const int*   sv = (const int*)d_in[6];
    float* out = (float*)d_out;

    const int gemm_smem = 4*128*PITCH*(int)sizeof(float);  // 73728 B
    const int attn_smem = SMEM_FLOATS * (int)sizeof(float);
    cudaFuncSetAttribute((const void*)qkv_kernel,
                         cudaFuncAttributeMaxDynamicSharedMemorySize, gemm_smem);
    cudaFuncSetAttribute((const void*)proj_kernel,
                         cudaFuncAttributeMaxDynamicSharedMemorySize, gemm_smem);
    cudaFuncSetAttribute((const void*)attn_kernel,
                         cudaFuncAttributeMaxDynamicSharedMemorySize, attn_smem);

    cis_kernel<<<(NT*32 + 255)/256, 256>>>();
    qkv_kernel<<<dim3((NM + 127)/128, NC/128, 3), 128, gemm_smem>>>(x, Wq, Wk, Wv);
    attn_kernel<<<dim3((NT + 63)/64, NH, NB), 256, attn_smem>>>(sv);
    proj_kernel<<<dim3((NM + 127)/128, NC/128), 128, gemm_smem>>>(Wo, bo, out);
}

// round 4
// speedup vs baseline: 1.2008x; 1.0184x over previous
#include <cuda_runtime.h>
#include <math.h>
#include <stdint.h>

#define NB 8
#define NT 1221
#define NC 1024
#define NH 16
#define ND 64
#define NM (NB*NT)      // 9768
#define HV 6            // int(16*0.4)
#define VTS 12          // HV + int(16*0.4)

#define PITCH 36        // smem row pitch (floats) -> conflict-free tf32 fragment lds
#define KTILE 32
#define NKT   (NC/KTILE)
#define BM 128
#define BN 64

// ---------------- scratch (device globals; no allocation allowed) ------------
__device__ float g_q[NB*NH*NT*ND];   // [B,H,T,D]
__device__ float g_k[NB*NH*NT*ND];
__device__ float g_v[NB*NH*NT*ND];
__device__ float g_ao[NM*NC];        // attention out, [B*T, H*D]
__device__ float g_cs[NT*32];        // rope cos [T, D/2]
__device__ float g_sn[NT*32];        // rope sin

// ---------------- small helpers ----------------------------------------------
__device__ __forceinline__ uint32_t f2tf32(float x) {
    uint32_t u;
    asm("cvt.rna.tf32.f32 %0, %1;" : "=r"(u) : "f"(x));
    return u;
}
__device__ __forceinline__ void split_tf32(float x, uint32_t& hi, uint32_t& lo) {
    hi = f2tf32(x);
    float r = x - __uint_as_float(hi);
    lo = f2tf32(r);
}
__device__ __forceinline__ void mma8(float* d,
                                     uint32_t a0, uint32_t a1, uint32_t a2, uint32_t a3,
                                     uint32_t b0, uint32_t b1) {
    asm volatile(
        "mma.sync.aligned.m16n8k8.row.col.f32.tf32.tf32.f32 "
        "{%0,%1,%2,%3},{%4,%5,%6,%7},{%8,%9},{%0,%1,%2,%3};\n"
        : "+f"(d[0]), "+f"(d[1]), "+f"(d[2]), "+f"(d[3])
        : "r"(a0), "r"(a1), "r"(a2), "r"(a3), "r"(b0), "r"(b1));
}
__device__ __forceinline__ void cpa16(float* dst, const float* src, bool pred) {
    uint32_t d = (uint32_t)__cvta_generic_to_shared(dst);
    int sz = pred ? 16 : 0;
    asm volatile("cp.async.cg.shared.global [%0], [%1], 16, %2;\n"
                 :: "r"(d), "l"(src), "r"(sz));
}
#define CP_COMMIT() asm volatile("cp.async.commit_group;\n")

// ---------------- rope table -------------------------------------------------
__global__ void cis_kernel() {
    int idx = blockIdx.x*256 + threadIdx.x;
    if (idx >= NT*32) return;
    int t = idx >> 5;
    int i = idx & 31;
    float inv = powf(10000.0f, -((float)(2*i) / 64.0f));
    float ang = (float)t * inv;
    float s, c;
    sincosf(ang, &s, &c);
    g_cs[idx] = c;
    g_sn[idx] = s;
}

// ---------------- shared 3xTF32 GEMM mainloop (128x64 tile) ------------------
// acc = A[m0:m0+128, :] @ B[n0:n0+64, :]^T.  128 thr, 4 warps 2x2,
// warp tile 64x32 (mi:4, ni:4), m16n8k8 TF32, pass-major 3xTF32.
__device__ __forceinline__ void gemm_main(
    const float* __restrict__ A, const float* __restrict__ Bw,
    int m0, int n0, float* sA, float* sB, float acc[4][4][4])
{
    const int tid  = threadIdx.x;
    const int lane = tid & 31;
    const int warp = tid >> 5;
    const int wm = (warp >> 1) * 64;
    const int wn = (warp & 1) * 32;
    const int g = lane >> 2;   // 0..7
    const int t = lane & 3;    // 0..3

    const bool pa = (m0 + tid) < NM;
    const float* arow = A  + (size_t)(m0 + tid) * NC;
    const float* brow = Bw + (size_t)(n0 + (tid >> 1)) * NC;
    const int bseg = (tid & 1) * 16;

    // prologue: stage 0
    {
        float* da = sA + tid*PITCH;
        float* db = sB + (tid >> 1)*PITCH + bseg;
        #pragma unroll
        for (int i = 0; i < 8; i++) cpa16(da + i*4, arow + i*4, pa);
        #pragma unroll
        for (int i = 0; i < 4; i++) cpa16(db + i*4, brow + bseg + i*4, true);
        CP_COMMIT();
    }

    for (int kt = 0; kt < NKT; kt++) {
        const int buf = kt & 1;
        if (kt + 1 < NKT) {
            const int k0n = (kt + 1) * KTILE;
            float* da = sA + (buf^1)*BM*PITCH + tid*PITCH;
            float* db = sB + (buf^1)*BN*PITCH + (tid >> 1)*PITCH + bseg;
            #pragma unroll
            for (int i = 0; i < 8; i++) cpa16(da + i*4, arow + k0n + i*4, pa);
            #pragma unroll
            for (int i = 0; i < 4; i++) cpa16(db + i*4, brow + k0n + bseg + i*4, true);
            CP_COMMIT();
            asm volatile("cp.async.wait_group 1;\n" ::: "memory");
        } else {
            asm volatile("cp.async.wait_group 0;\n" ::: "memory");
        }
        __syncthreads();

        const float* tA = sA + buf*BM*PITCH;
        const float* tB = sB + buf*BN*PITCH;

        #pragma unroll
        for (int ks = 0; ks < 4; ks++) {
            uint32_t ah[4][4], al[4][4], bh[4][2], bl[4][2];
            #pragma unroll
            for (int mi = 0; mi < 4; mi++) {
                const int r0 = wm + mi*16 + g;
                float x0 = tA[(r0    )*PITCH + ks*8 + t    ];
                float x1 = tA[(r0 + 8)*PITCH + ks*8 + t    ];
                float x2 = tA[(r0    )*PITCH + ks*8 + t + 4];
                float x3 = tA[(r0 + 8)*PITCH + ks*8 + t + 4];
                split_tf32(x0, ah[mi][0], al[mi][0]);
                split_tf32(x1, ah[mi][1], al[mi][1]);
                split_tf32(x2, ah[mi][2], al[mi][2]);
                split_tf32(x3, ah[mi][3], al[mi][3]);
            }
            #pragma unroll
            for (int ni = 0; ni < 4; ni++) {
                const int r = wn + ni*8 + g;
                float y0 = tB[r*PITCH + ks*8 + t    ];
                float y1 = tB[r*PITCH + ks*8 + t + 4];
                split_tf32(y0, bh[ni][0], bl[ni][0]);
                split_tf32(y1, bh[ni][1], bl[ni][1]);
            }
            // pass-major: 16 independent mma per pass -> no back-to-back
            // same-accumulator chains
            #pragma unroll
            for (int mi = 0; mi < 4; mi++)
                #pragma unroll
                for (int ni = 0; ni < 4; ni++)
                    mma8(acc[mi][ni], ah[mi][0], ah[mi][1], ah[mi][2], ah[mi][3],
                         bh[ni][0], bh[ni][1]);
            #pragma unroll
            for (int mi = 0; mi < 4; mi++)
                #pragma unroll
                for (int ni = 0; ni < 4; ni++)
                    mma8(acc[mi][ni], al[mi][0], al[mi][1], al[mi][2], al[mi][3],
                         bh[ni][0], bh[ni][1]);
            #pragma unroll
            for (int mi = 0; mi < 4; mi++)
                #pragma unroll
                for (int ni = 0; ni < 4; ni++)
                    mma8(acc[mi][ni], ah[mi][0], ah[mi][1], ah[mi][2], ah[mi][3],
                         bl[ni][0], bl[ni][1]);
        }
        __syncthreads();
    }
}

// ---------------- fused QKV GEMM (tensor core) + RoPE + head transpose -------
__global__ __launch_bounds__(128, 4) void qkv_kernel(
    const float* __restrict__ X,
    const float* __restrict__ Wq,
    const float* __restrict__ Wk,
    const float* __restrict__ Wv)
{
    extern __shared__ float sm[];
    float* sA = sm;
    float* sB = sm + 2*BM*PITCH;

    const int which = blockIdx.z;
    const float* __restrict__ W = (which==0) ? Wq : ((which==1) ? Wk : Wv);
    float* __restrict__ dst = (which==0) ? g_q : ((which==1) ? g_k : g_v);

    const int m0 = blockIdx.x * BM;
    const int n0 = blockIdx.y * BN;

    float acc[4][4][4];
    #pragma unroll
    for (int mi = 0; mi < 4; mi++)
        #pragma unroll
        for (int ni = 0; ni < 4; ni++)
            #pragma unroll
            for (int j = 0; j < 4; j++) acc[mi][ni][j] = 0.f;

    gemm_main(X, W, m0, n0, sA, sB, acc);

    const int tid  = threadIdx.x;
    const int lane = tid & 31;
    const int warp = tid >> 5;
    const int wm = (warp >> 1) * 64;
    const int wn = (warp & 1) * 32;
    const int g = lane >> 2;
    const int t = lane & 3;

    #pragma unroll
    for (int mi = 0; mi < 4; mi++) {
        #pragma unroll
        for (int half = 0; half < 2; half++) {
            const int m = m0 + wm + mi*16 + g + half*8;
            if (m >= NM) continue;
            const int bb  = m / NT;
            const int tok = m - bb*NT;
            #pragma unroll
            for (int ni = 0; ni < 4; ni++) {
                const int n = n0 + wn + ni*8 + 2*t;
                const int h = n >> 6, d = n & 63;
                float e = acc[mi][ni][half*2 + 0];
                float o = acc[mi][ni][half*2 + 1];
                float oe, oo;
                if (which < 2) {
                    float cv = g_cs[tok*32 + (d >> 1)];
                    float sv = g_sn[tok*32 + (d >> 1)];
                    oe = e*cv - o*sv;
                    oo = e*sv + o*cv;
                } else { oe = e; oo = o; }
                float2* p = (float2*)&dst[((size_t)((bb*NH + h)*NT) + tok)*ND + d];
                *p = make_float2(oe, oo);
            }
        }
    }
}

// ---------------- output projection (tensor core): out = AO @ Wo^T + bo ------
__global__ __launch_bounds__(128, 4) void proj_kernel(
    const float* __restrict__ W,
    const float* __restrict__ bias,
    float* __restrict__ out)
{
    extern __shared__ float sm[];
    float* sA = sm;
    float* sB = sm + 2*BM*PITCH;

    const int m0 = blockIdx.x * BM;
    const int n0 = blockIdx.y * BN;

    float acc[4][4][4];
    #pragma unroll
    for (int mi = 0; mi < 4; mi++)
        #pragma unroll
        for (int ni = 0; ni < 4; ni++)
            #pragma unroll
            for (int j = 0; j < 4; j++) acc[mi][ni][j] = 0.f;

    gemm_main(g_ao, W, m0, n0, sA, sB, acc);

    const int tid  = threadIdx.x;
    const int lane = tid & 31;
    const int warp = tid >> 5;
    const int wm = (warp >> 1) * 64;
    const int wn = (warp & 1) * 32;
    const int g = lane >> 2;
    const int t = lane & 3;

    #pragma unroll
    for (int mi = 0; mi < 4; mi++) {
        #pragma unroll
        for (int half = 0; half < 2; half++) {
            const int m = m0 + wm + mi*16 + g + half*8;
            if (m >= NM) continue;
            #pragma unroll
            for (int ni = 0; ni < 4; ni++) {
                const int n = n0 + wn + ni*8 + 2*t;
                float b0 = bias[n], b1 = bias[n+1];
                float2 r = make_float2(acc[mi][ni][half*2 + 0] + b0,
                                       acc[mi][ni][half*2 + 1] + b1);
                *(float2*)&out[(size_t)m*NC + n] = r;
            }
        }
    }
}

// ---------------- attention: flash-style with modality mask ------------------
#define SMEM_FLOATS (3*64*68 + 64*64)

__global__ __launch_bounds__(256) void attn_kernel(const int* __restrict__ svp)
{
    extern __shared__ float smf[];
    float* sQt = smf;                 // [d][r], pitch 68
    float* sKt = smf + 64*68;         // [d][c], pitch 68
    float* sP  = smf + 2*64*68;       // [r][c], pitch 68
    float* sV  = smf + 3*64*68;       // [kv][dv], pitch 64

    const int S_V = *svp;
    const int qt = blockIdx.x, h = blockIdx.y, b = blockIdx.z;
    const int q0 = qt * 64;
    const int tid = threadIdx.x;
    const int tr = tid >> 4;
    const int tc = tid & 15;

    const size_t base = (size_t)((b*NH + h)*NT) * ND;
    const float* __restrict__ Qb = g_q + base;
    const float* __restrict__ Kb = g_k + base;
    const float* __restrict__ Vb = g_v + base;

    #pragma unroll
    for (int it = 0; it < 16; it++) {
        int idx = it*256 + tid;
        int r = idx >> 6, d = idx & 63;
        int q = q0 + r;
        sQt[d*68 + r] = (q < NT) ? Qb[(size_t)q*ND + d] : 0.f;
    }

    float m_i[4], l_i[4], o[4][4];
    #pragma unroll
    for (int i = 0; i < 4; i++) {
        m_i[i] = -1e30f; l_i[i] = 0.f;
        #pragma unroll
        for (int j = 0; j < 4; j++) o[i][j] = 0.f;
    }

    const int ceil_sv = (S_V + 63) >> 6;
    int kv_lo = 0, kv_hi = 0;
    if (h < HV) {
        if (q0 < S_V) { kv_lo = 0; kv_hi = ceil_sv; }
    } else if (h < VTS) {
        if (q0 + 63 >= S_V) { kv_lo = S_V >> 6; kv_hi = qt + 1; }
    } else {
        kv_lo = 0; kv_hi = (qt + 1 > ceil_sv) ? (qt + 1) : ceil_sv;
    }
    __syncthreads();

    for (int kvt = kv_lo; kvt < kv_hi; kvt++) {
        const int kv0 = kvt * 64;
        #pragma unroll
        for (int it = 0; it < 16; it++) {
            int idx = it*256 + tid;
            int c = idx >> 6, d = idx & 63;
            int kv = kv0 + c;
            float kx = (kv < NT) ? Kb[(size_t)kv*ND + d] : 0.f;
            float vx = (kv < NT) ? Vb[(size_t)kv*ND + d] : 0.f;
            sKt[d*68 + c] = kx;
            sV[c*64 + d]  = vx;
        }
        __syncthreads();

        float s[4][4];
        #pragma unroll
        for (int i = 0; i < 4; i++)
            #pragma unroll
            for (int j = 0; j < 4; j++) s[i][j] = 0.f;

        #pragma unroll 16
        for (int d = 0; d < 64; d++) {
            float4 a  = *(const float4*)&sQt[d*68 + tr*4];
            float4 bb = *(const float4*)&sKt[d*68 + tc*4];
            float av[4] = {a.x, a.y, a.z, a.w};
            float bv[4] = {bb.x, bb.y, bb.z, bb.w};
            #pragma unroll
            for (int i = 0; i < 4; i++)
                #pragma unroll
                for (int j = 0; j < 4; j++)
                    s[i][j] += av[i]*bv[j];
        }

        #pragma unroll
        for (int i = 0; i < 4; i++) {
            int q = q0 + tr*4 + i;
            #pragma unroll
            for (int j = 0; j < 4; j++) {
                int kv = kv0 + tc*4 + j;
                bool ok;
                if (h < HV)        ok = (q < S_V) && (kv < S_V);
                else if (h < VTS)  ok = (q >= S_V) && (kv >= S_V) && (q >= kv);
                else               ok = (kv < S_V) || (q >= kv);
                ok = ok && (kv < NT) && (q < NT);
                s[i][j] = ok ? s[i][j] * 0.125f : -1e30f;
            }
        }

        #pragma unroll
        for (int i = 0; i < 4; i++) {
            float rm = fmaxf(fmaxf(s[i][0], s[i][1]), fmaxf(s[i][2], s[i][3]));
            rm = fmaxf(rm, __shfl_xor_sync(0xffffffffu, rm, 8));
            rm = fmaxf(rm, __shfl_xor_sync(0xffffffffu, rm, 4));
            rm = fmaxf(rm, __shfl_xor_sync(0xffffffffu, rm, 2));
            rm = fmaxf(rm, __shfl_xor_sync(0xffffffffu, rm, 1));
            float mnew = fmaxf(m_i[i], rm);
            float alpha = __expf(m_i[i] - mnew);
            m_i[i] = mnew;
            float psum = 0.f;
            #pragma unroll
            for (int j = 0; j < 4; j++) {
                float p = __expf(s[i][j] - mnew);
                s[i][j] = p;
                psum += p;
            }
            psum += __shfl_xor_sync(0xffffffffu, psum, 8);
            psum += __shfl_xor_sync(0xffffffffu, psum, 4);
            psum += __shfl_xor_sync(0xffffffffu, psum, 2);
            psum += __shfl_xor_sync(0xffffffffu, psum, 1);
            l_i[i] = l_i[i]*alpha + psum;
            #pragma unroll
            for (int j = 0; j < 4; j++) o[i][j] *= alpha;
        }

        #pragma unroll
        for (int i = 0; i < 4; i++)
            #pragma unroll
            for (int j = 0; j < 4; j++)
                sP[(tr*4+i)*68 + tc*4 + j] = s[i][j];
        __syncthreads();

        #pragma unroll 8
        for (int kv = 0; kv < 64; kv++) {
            float p0 = sP[(tr*4+0)*68 + kv];
            float p1 = sP[(tr*4+1)*68 + kv];
            float p2 = sP[(tr*4+2)*68 + kv];
            float p3 = sP[(tr*4+3)*68 + kv];
            float4 v4 = *(const float4*)&sV[kv*64 + tc*4];
            o[0][0] += p0*v4.x; o[0][1] += p0*v4.y; o[0][2] += p0*v4.z; o[0][3] += p0*v4.w;
            o[1][0] += p1*v4.x; o[1][1] += p1*v4.y; o[1][2] += p1*v4.z; o[1][3] += p1*v4.w;
            o[2][0] += p2*v4.x; o[2][1] += p2*v4.y; o[2][2] += p2*v4.z; o[2][3] += p2*v4.w;
            o[3][0] += p3*v4.x; o[3][1] += p3*v4.y; o[3][2] += p3*v4.z; o[3][3] += p3*v4.w;
        }
        __syncthreads();
    }

    float* __restrict__ Ob = g_ao + (size_t)(b*NT)*NC + h*ND;
    #pragma unroll
    for (int i = 0; i < 4; i++) {
        int q = q0 + tr*4 + i;
        if (q >= NT) continue;
        float invl = (m_i[i] > -5e29f) ? (1.f / l_i[i]) : 0.f;
        float4 r4 = make_float4(o[i][0]*invl, o[i][1]*invl, o[i][2]*invl, o[i][3]*invl);
        *(float4*)&Ob[(size_t)q*NC + tc*4] = r4;
    }
}

// ---------------- launch -----------------------------------------------------
extern "C" void kernel_launch(void* const* d_in, const int* in_sizes, int n_in,
                              void* d_out, int out_size) {
    const float* x  = (const float*)d_in[0];
    const float* Wq = (const float*)d_in[1];
    const float* Wk = (const float*)d_in[2];
    const float* Wv = (const float*)d_in[3];
    const float* Wo = (const float*)d_in[4];
    const float* bo = (const float*)d_in[5];
    const int*   sv = (const int*)d_in[6];
    float* out = (float*)d_out;

    const int gemm_smem = (2*BM*PITCH + 2*BN*PITCH)*(int)sizeof(float);  // 55296 B
    const int attn_smem = SMEM_FLOATS * (int)sizeof(float);
    cudaFuncSetAttribute((const void*)qkv_kernel,
                         cudaFuncAttributeMaxDynamicSharedMemorySize, gemm_smem);
    cudaFuncSetAttribute((const void*)proj_kernel,
                         cudaFuncAttributeMaxDynamicSharedMemorySize, gemm_smem);
    cudaFuncSetAttribute((const void*)attn_kernel,
                         cudaFuncAttributeMaxDynamicSharedMemorySize, attn_smem);

    cis_kernel<<<(NT*32 + 255)/256, 256>>>();
    qkv_kernel<<<dim3((NM + BM - 1)/BM, NC/BN, 3), 128, gemm_smem>>>(x, Wq, Wk, Wv);
    attn_kernel<<<dim3((NT + 63)/64, NH, NB), 256, attn_smem>>>(sv);
    proj_kernel<<<dim3((NM + BM - 1)/BM, NC/BN), 128, gemm_smem>>>(Wo, bo, out);
}

// round 7
// speedup vs baseline: 1.5151x; 1.2617x over previous
#include <cuda_runtime.h>
#include <cuda_bf16.h>
#include <math.h>
#include <stdint.h>

#define NB 8
#define NT 1221
#define NC 1024
#define NH 16
#define ND 64
#define NM (NB*NT)      // 9768
#define HV 6
#define VTS 12

#define BM 128
#define BN 64
#define KTILE 32
#define NKT (NC/KTILE)  // 32
#define PITCH 40        // bf16 elems per smem row (80 B) -> conflict-free frags

// ---------------- scratch (device globals; no allocation allowed) ------------
__device__ float g_q[NB*NH*NT*ND];
__device__ float g_k[NB*NH*NT*ND];
__device__ float g_v[NB*NH*NT*ND];
__device__ float g_cs[NT*32];
__device__ float g_sn[NT*32];
__device__ __nv_bfloat16 g_xh[(size_t)NM*NC];   // A operand hi (X, later attn-out)
__device__ __nv_bfloat16 g_xl[(size_t)NM*NC];   // A operand lo
__device__ __nv_bfloat16 g_wh[4*(size_t)NC*NC]; // Wq,Wk,Wv,Wo hi
__device__ __nv_bfloat16 g_wl[4*(size_t)NC*NC]; // lo

// ---------------- helpers ----------------------------------------------------
__device__ __forceinline__ void mma16(float* d,
                                      uint32_t a0, uint32_t a1, uint32_t a2, uint32_t a3,
                                      uint32_t b0, uint32_t b1) {
    asm volatile(
        "mma.sync.aligned.m16n8k16.row.col.f32.bf16.bf16.f32 "
        "{%0,%1,%2,%3},{%4,%5,%6,%7},{%8,%9},{%0,%1,%2,%3};\n"
        : "+f"(d[0]), "+f"(d[1]), "+f"(d[2]), "+f"(d[3])
        : "r"(a0), "r"(a1), "r"(a2), "r"(a3), "r"(b0), "r"(b1));
}
__device__ __forceinline__ void cpa16(__nv_bfloat16* dst, const __nv_bfloat16* src, bool pred) {
    uint32_t d = (uint32_t)__cvta_generic_to_shared(dst);
    int sz = pred ? 16 : 0;
    asm volatile("cp.async.cg.shared.global [%0], [%1], 16, %2;\n"
                 :: "r"(d), "l"(src), "r"(sz));
}
#define CP_COMMIT() asm volatile("cp.async.commit_group;\n")

// smem layout (bf16 elements): 2 stages of {AH 128*40, AL 128*40, BH 64*40, BL 64*40}
#define A_ELE (BM*PITCH)          // 5120
#define B_ELE (BN*PITCH)          // 2560
#define STAGE_ELE (2*A_ELE + 2*B_ELE)  // 15360
#define AH_E(s) ((s)*STAGE_ELE)
#define AL_E(s) (AH_E(s) + A_ELE)
#define BH_E(s) (AH_E(s) + 2*A_ELE)
#define BL_E(s) (AH_E(s) + 2*A_ELE + B_ELE)
#define SMEM_GEMM (2*STAGE_ELE*2) // bytes = 61440

// ---------------- rope table -------------------------------------------------
__global__ void cis_kernel() {
    int idx = blockIdx.x*256 + threadIdx.x;
    if (idx >= NT*32) return;
    int t = idx >> 5;
    int i = idx & 31;
    float inv = powf(10000.0f, -((float)(2*i) / 64.0f));
    float ang = (float)t * inv;
    float s, c;
    sincosf(ang, &s, &c);
    g_cs[idx] = c;
    g_sn[idx] = s;
}

// ---------------- fp32 -> (bf16 hi, bf16 lo) conversion ----------------------
__global__ __launch_bounds__(256) void cvt_kernel(
    const float* __restrict__ x,  const float* __restrict__ wq,
    const float* __restrict__ wk, const float* __restrict__ wv,
    const float* __restrict__ wo)
{
    const int seg = blockIdx.y;
    const float* src;
    __nv_bfloat16 *hi, *lo;
    size_t n;
    if (seg == 0) { src = x;  hi = g_xh; lo = g_xl; n = (size_t)NM*NC; }
    else {
        src = (seg==1) ? wq : (seg==2) ? wk : (seg==3) ? wv : wo;
        hi = g_wh + (size_t)(seg-1)*NC*NC;
        lo = g_wl + (size_t)(seg-1)*NC*NC;
        n = (size_t)NC*NC;
    }
    size_t i = ((size_t)blockIdx.x*256 + threadIdx.x) * 4;
    if (i >= n) return;
    float4 v = *(const float4*)(src + i);
    __nv_bfloat16 h0 = __float2bfloat16(v.x); __nv_bfloat16 l0 = __float2bfloat16(v.x - __bfloat162float(h0));
    __nv_bfloat16 h1 = __float2bfloat16(v.y); __nv_bfloat16 l1 = __float2bfloat16(v.y - __bfloat162float(h1));
    __nv_bfloat16 h2 = __float2bfloat16(v.z); __nv_bfloat16 l2 = __float2bfloat16(v.z - __bfloat162float(h2));
    __nv_bfloat16 h3 = __float2bfloat16(v.w); __nv_bfloat16 l3 = __float2bfloat16(v.w - __bfloat162float(h3));
    uint2 hp, lp;
    hp.x = (uint32_t)__bfloat16_as_ushort(h0) | ((uint32_t)__bfloat16_as_ushort(h1) << 16);
    hp.y = (uint32_t)__bfloat16_as_ushort(h2) | ((uint32_t)__bfloat16_as_ushort(h3) << 16);
    lp.x = (uint32_t)__bfloat16_as_ushort(l0) | ((uint32_t)__bfloat16_as_ushort(l1) << 16);
    lp.y = (uint32_t)__bfloat16_as_ushort(l2) | ((uint32_t)__bfloat16_as_ushort(l3) << 16);
    *(uint2*)(hi + i) = hp;
    *(uint2*)(lo + i) = lp;
}

// ---------------- 3-pass bf16-split GEMM mainloop (mma.m16n8k16) -------------
// acc = A[m0:+128, :] @ B[n0:+64, :]^T.  128 thr, 4 warps 2x2 (64x32 warp tile).
__device__ __forceinline__ void gemm_main(
    const __nv_bfloat16* __restrict__ Ah, const __nv_bfloat16* __restrict__ Al,
    const __nv_bfloat16* __restrict__ Bh, const __nv_bfloat16* __restrict__ Bl,
    int m0, int n0, __nv_bfloat16* sm, float acc[4][4][4])
{
    const int tid  = threadIdx.x;
    const int lane = tid & 31;
    const int warp = tid >> 5;
    const int wm = (warp >> 1) * 64;
    const int wn = (warp & 1) * 32;
    const int g = lane >> 2;   // 0..7
    const int t = lane & 3;    // 0..3

    const bool pa = (m0 + tid) < NM;
    const __nv_bfloat16* arh = Ah + (size_t)(m0 + tid) * NC;
    const __nv_bfloat16* arl = Al + (size_t)(m0 + tid) * NC;
    const int brr = tid >> 1;               // 0..63
    const int bc0 = (tid & 1) * 2;          // chunk pair 0/2
    const __nv_bfloat16* brh = Bh + (size_t)(n0 + brr) * NC;
    const __nv_bfloat16* brl = Bl + (size_t)(n0 + brr) * NC;

    // prologue: stage 0
    {
        __nv_bfloat16* dah = sm + AH_E(0) + tid*PITCH;
        __nv_bfloat16* dal = sm + AL_E(0) + tid*PITCH;
        #pragma unroll
        for (int c = 0; c < 4; c++) {
            cpa16(dah + c*8, arh + c*8, pa);
            cpa16(dal + c*8, arl + c*8, pa);
        }
        __nv_bfloat16* dbh = sm + BH_E(0) + brr*PITCH + bc0*8;
        __nv_bfloat16* dbl = sm + BL_E(0) + brr*PITCH + bc0*8;
        #pragma unroll
        for (int c = 0; c < 2; c++) {
            cpa16(dbh + c*8, brh + (bc0 + c)*8, true);
            cpa16(dbl + c*8, brl + (bc0 + c)*8, true);
        }
        CP_COMMIT();
    }

    for (int kt = 0; kt < NKT; kt++) {
        const int buf = kt & 1;
        if (kt + 1 < NKT) {
            const int k0n = (kt + 1) * KTILE;
            const int s2 = buf ^ 1;
            __nv_bfloat16* dah = sm + AH_E(s2) + tid*PITCH;
            __nv_bfloat16* dal = sm + AL_E(s2) + tid*PITCH;
            #pragma unroll
            for (int c = 0; c < 4; c++) {
                cpa16(dah + c*8, arh + k0n + c*8, pa);
                cpa16(dal + c*8, arl + k0n + c*8, pa);
            }
            __nv_bfloat16* dbh = sm + BH_E(s2) + brr*PITCH + bc0*8;
            __nv_bfloat16* dbl = sm + BL_E(s2) + brr*PITCH + bc0*8;
            #pragma unroll
            for (int c = 0; c < 2; c++) {
                cpa16(dbh + c*8, brh + k0n + (bc0 + c)*8, true);
                cpa16(dbl + c*8, brl + k0n + (bc0 + c)*8, true);
            }
            CP_COMMIT();
            asm volatile("cp.async.wait_group 1;\n" ::: "memory");
        } else {
            asm volatile("cp.async.wait_group 0;\n" ::: "memory");
        }
        __syncthreads();

        const __nv_bfloat16* tAh = sm + AH_E(buf);
        const __nv_bfloat16* tAl = sm + AL_E(buf);
        const __nv_bfloat16* tBh = sm + BH_E(buf);
        const __nv_bfloat16* tBl = sm + BL_E(buf);

        #pragma unroll
        for (int ks = 0; ks < 2; ks++) {
            const int kb = ks*16 + 2*t;
            uint32_t ah[4][4], al[4][4], bh[4][2], bl[4][2];
            #pragma unroll
            for (int mi = 0; mi < 4; mi++) {
                const int r0 = (wm + mi*16 + g) * PITCH;
                const int r1 = r0 + 8*PITCH;
                ah[mi][0] = *(const uint32_t*)&tAh[r0 + kb];
                ah[mi][1] = *(const uint32_t*)&tAh[r1 + kb];
                ah[mi][2] = *(const uint32_t*)&tAh[r0 + kb + 8];
                ah[mi][3] = *(const uint32_t*)&tAh[r1 + kb + 8];
                al[mi][0] = *(const uint32_t*)&tAl[r0 + kb];
                al[mi][1] = *(const uint32_t*)&tAl[r1 + kb];
                al[mi][2] = *(const uint32_t*)&tAl[r0 + kb + 8];
                al[mi][3] = *(const uint32_t*)&tAl[r1 + kb + 8];
            }
            #pragma unroll
            for (int ni = 0; ni < 4; ni++) {
                const int r = (wn + ni*8 + g) * PITCH;
                bh[ni][0] = *(const uint32_t*)&tBh[r + kb];
                bh[ni][1] = *(const uint32_t*)&tBh[r + kb + 8];
                bl[ni][0] = *(const uint32_t*)&tBl[r + kb];
                bl[ni][1] = *(const uint32_t*)&tBl[r + kb + 8];
            }
            // pass-major: 16 independent mma per pass
            #pragma unroll
            for (int mi = 0; mi < 4; mi++)
                #pragma unroll
                for (int ni = 0; ni < 4; ni++)
                    mma16(acc[mi][ni], ah[mi][0], ah[mi][1], ah[mi][2], ah[mi][3],
                          bh[ni][0], bh[ni][1]);
            #pragma unroll
            for (int mi = 0; mi < 4; mi++)
                #pragma unroll
                for (int ni = 0; ni < 4; ni++)
                    mma16(acc[mi][ni], al[mi][0], al[mi][1], al[mi][2], al[mi][3],
                          bh[ni][0], bh[ni][1]);
            #pragma unroll
            for (int mi = 0; mi < 4; mi++)
                #pragma unroll
                for (int ni = 0; ni < 4; ni++)
                    mma16(acc[mi][ni], ah[mi][0], ah[mi][1], ah[mi][2], ah[mi][3],
                          bl[ni][0], bl[ni][1]);
        }
        __syncthreads();
    }
}

// ---------------- fused QKV GEMM + RoPE + head transpose ---------------------
__global__ __launch_bounds__(128, 3) void qkv_kernel()
{
    extern __shared__ __nv_bfloat16 sm[];
    const int which = blockIdx.z;
    const __nv_bfloat16* Bh = g_wh + (size_t)which*NC*NC;
    const __nv_bfloat16* Bl = g_wl + (size_t)which*NC*NC;
    float* __restrict__ dst = (which==0) ? g_q : ((which==1) ? g_k : g_v);

    const int m0 = blockIdx.y * BM;
    const int n0 = blockIdx.x * BN;

    float acc[4][4][4];
    #pragma unroll
    for (int mi = 0; mi < 4; mi++)
        #pragma unroll
        for (int ni = 0; ni < 4; ni++)
            #pragma unroll
            for (int j = 0; j < 4; j++) acc[mi][ni][j] = 0.f;

    gemm_main(g_xh, g_xl, Bh, Bl, m0, n0, sm, acc);

    const int tid  = threadIdx.x;
    const int lane = tid & 31;
    const int warp = tid >> 5;
    const int wm = (warp >> 1) * 64;
    const int wn = (warp & 1) * 32;
    const int g = lane >> 2;
    const int t = lane & 3;

    #pragma unroll
    for (int mi = 0; mi < 4; mi++) {
        #pragma unroll
        for (int half = 0; half < 2; half++) {
            const int m = m0 + wm + mi*16 + g + half*8;
            if (m >= NM) continue;
            const int bb  = m / NT;
            const int tok = m - bb*NT;
            #pragma unroll
            for (int ni = 0; ni < 4; ni++) {
                const int n = n0 + wn + ni*8 + 2*t;
                const int h = n >> 6, d = n & 63;
                float e = acc[mi][ni][half*2 + 0];
                float o = acc[mi][ni][half*2 + 1];
                float oe, oo;
                if (which < 2) {
                    float cv = g_cs[tok*32 + (d >> 1)];
                    float sv = g_sn[tok*32 + (d >> 1)];
                    oe = e*cv - o*sv;
                    oo = e*sv + o*cv;
                } else { oe = e; oo = o; }
                float2* p = (float2*)&dst[((size_t)((bb*NH + h)*NT) + tok)*ND + d];
                *p = make_float2(oe, oo);
            }
        }
    }
}

// ---------------- output projection: out = AO @ Wo^T + bo --------------------
__global__ __launch_bounds__(128, 3) void proj_kernel(
    const float* __restrict__ bias, float* __restrict__ out)
{
    extern __shared__ __nv_bfloat16 sm[];
    const __nv_bfloat16* Bh = g_wh + (size_t)3*NC*NC;
    const __nv_bfloat16* Bl = g_wl + (size_t)3*NC*NC;

    const int m0 = blockIdx.y * BM;
    const int n0 = blockIdx.x * BN;

    float acc[4][4][4];
    #pragma unroll
    for (int mi = 0; mi < 4; mi++)
        #pragma unroll
        for (int ni = 0; ni < 4; ni++)
            #pragma unroll
            for (int j = 0; j < 4; j++) acc[mi][ni][j] = 0.f;

    gemm_main(g_xh, g_xl, Bh, Bl, m0, n0, sm, acc);

    const int tid  = threadIdx.x;
    const int lane = tid & 31;
    const int warp = tid >> 5;
    const int wm = (warp >> 1) * 64;
    const int wn = (warp & 1) * 32;
    const int g = lane >> 2;
    const int t = lane & 3;

    #pragma unroll
    for (int mi = 0; mi < 4; mi++) {
        #pragma unroll
        for (int half = 0; half < 2; half++) {
            const int m = m0 + wm + mi*16 + g + half*8;
            if (m >= NM) continue;
            #pragma unroll
            for (int ni = 0; ni < 4; ni++) {
                const int n = n0 + wn + ni*8 + 2*t;
                float2 r = make_float2(acc[mi][ni][half*2 + 0] + bias[n],
                                       acc[mi][ni][half*2 + 1] + bias[n+1]);
                *(float2*)&out[(size_t)m*NC + n] = r;
            }
        }
    }
}

// ---------------- attention: flash-style with modality mask ------------------
#define SMEM_FLOATS (3*64*68 + 64*64)

__global__ __launch_bounds__(256) void attn_kernel(const int* __restrict__ svp)
{
    extern __shared__ float smf[];
    float* sQt = smf;                 // [d][r], pitch 68
    float* sKt = smf + 64*68;         // [d][c], pitch 68
    float* sP  = smf + 2*64*68;       // [r][c], pitch 68
    float* sV  = smf + 3*64*68;       // [kv][dv], pitch 64

    const int S_V = *svp;
    const int qt = blockIdx.x, h = blockIdx.y, b = blockIdx.z;
    const int q0 = qt * 64;
    const int tid = threadIdx.x;
    const int tr = tid >> 4;
    const int tc = tid & 15;

    const size_t base = (size_t)((b*NH + h)*NT) * ND;
    const float* __restrict__ Qb = g_q + base;
    const float* __restrict__ Kb = g_k + base;
    const float* __restrict__ Vb = g_v + base;

    #pragma unroll
    for (int it = 0; it < 16; it++) {
        int idx = it*256 + tid;
        int r = idx >> 6, d = idx & 63;
        int q = q0 + r;
        sQt[d*68 + r] = (q < NT) ? Qb[(size_t)q*ND + d] : 0.f;
    }

    float m_i[4], l_i[4], o[4][4];
    #pragma unroll
    for (int i = 0; i < 4; i++) {
        m_i[i] = -1e30f; l_i[i] = 0.f;
        #pragma unroll
        for (int j = 0; j < 4; j++) o[i][j] = 0.f;
    }

    const int ceil_sv = (S_V + 63) >> 6;
    int kv_lo = 0, kv_hi = 0;
    if (h < HV) {
        if (q0 < S_V) { kv_lo = 0; kv_hi = ceil_sv; }
    } else if (h < VTS) {
        if (q0 + 63 >= S_V) { kv_lo = S_V >> 6; kv_hi = qt + 1; }
    } else {
        kv_lo = 0; kv_hi = (qt + 1 > ceil_sv) ? (qt + 1) : ceil_sv;
    }
    __syncthreads();

    for (int kvt = kv_lo; kvt < kv_hi; kvt++) {
        const int kv0 = kvt * 64;
        #pragma unroll
        for (int it = 0; it < 16; it++) {
            int idx = it*256 + tid;
            int c = idx >> 6, d = idx & 63;
            int kv = kv0 + c;
            float kx = (kv < NT) ? Kb[(size_t)kv*ND + d] : 0.f;
            float vx = (kv < NT) ? Vb[(size_t)kv*ND + d] : 0.f;
            sKt[d*68 + c] = kx;
            sV[c*64 + d]  = vx;
        }
        __syncthreads();

        float s[4][4];
        #pragma unroll
        for (int i = 0; i < 4; i++)
            #pragma unroll
            for (int j = 0; j < 4; j++) s[i][j] = 0.f;

        #pragma unroll 16
        for (int d = 0; d < 64; d++) {
            float4 a  = *(const float4*)&sQt[d*68 + tr*4];
            float4 bb = *(const float4*)&sKt[d*68 + tc*4];
            float av[4] = {a.x, a.y, a.z, a.w};
            float bv[4] = {bb.x, bb.y, bb.z, bb.w};
            #pragma unroll
            for (int i = 0; i < 4; i++)
                #pragma unroll
                for (int j = 0; j < 4; j++)
                    s[i][j] += av[i]*bv[j];
        }

        #pragma unroll
        for (int i = 0; i < 4; i++) {
            int q = q0 + tr*4 + i;
            #pragma unroll
            for (int j = 0; j < 4; j++) {
                int kv = kv0 + tc*4 + j;
                bool ok;
                if (h < HV)        ok = (q < S_V) && (kv < S_V);
                else if (h < VTS)  ok = (q >= S_V) && (kv >= S_V) && (q >= kv);
                else               ok = (kv < S_V) || (q >= kv);
                ok = ok && (kv < NT) && (q < NT);
                s[i][j] = ok ? s[i][j] * 0.125f : -1e30f;
            }
        }

        #pragma unroll
        for (int i = 0; i < 4; i++) {
            float rm = fmaxf(fmaxf(s[i][0], s[i][1]), fmaxf(s[i][2], s[i][3]));
            rm = fmaxf(rm, __shfl_xor_sync(0xffffffffu, rm, 8));
            rm = fmaxf(rm, __shfl_xor_sync(0xffffffffu, rm, 4));
            rm = fmaxf(rm, __shfl_xor_sync(0xffffffffu, rm, 2));
            rm = fmaxf(rm, __shfl_xor_sync(0xffffffffu, rm, 1));
            float mnew = fmaxf(m_i[i], rm);
            float alpha = __expf(m_i[i] - mnew);
            m_i[i] = mnew;
            float psum = 0.f;
            #pragma unroll
            for (int j = 0; j < 4; j++) {
                float p = __expf(s[i][j] - mnew);
                s[i][j] = p;
                psum += p;
            }
            psum += __shfl_xor_sync(0xffffffffu, psum, 8);
            psum += __shfl_xor_sync(0xffffffffu, psum, 4);
            psum += __shfl_xor_sync(0xffffffffu, psum, 2);
            psum += __shfl_xor_sync(0xffffffffu, psum, 1);
            l_i[i] = l_i[i]*alpha + psum;
            #pragma unroll
            for (int j = 0; j < 4; j++) o[i][j] *= alpha;
        }

        #pragma unroll
        for (int i = 0; i < 4; i++)
            #pragma unroll
            for (int j = 0; j < 4; j++)
                sP[(tr*4+i)*68 + tc*4 + j] = s[i][j];
        __syncthreads();

        #pragma unroll 8
        for (int kv = 0; kv < 64; kv++) {
            float p0 = sP[(tr*4+0)*68 + kv];
            float p1 = sP[(tr*4+1)*68 + kv];
            float p2 = sP[(tr*4+2)*68 + kv];
            float p3 = sP[(tr*4+3)*68 + kv];
            float4 v4 = *(const float4*)&sV[kv*64 + tc*4];
            o[0][0] += p0*v4.x; o[0][1] += p0*v4.y; o[0][2] += p0*v4.z; o[0][3] += p0*v4.w;
            o[1][0] += p1*v4.x; o[1][1] += p1*v4.y; o[1][2] += p1*v4.z; o[1][3] += p1*v4.w;
            o[2][0] += p2*v4.x; o[2][1] += p2*v4.y; o[2][2] += p2*v4.z; o[2][3] += p2*v4.w;
            o[3][0] += p3*v4.x; o[3][1] += p3*v4.y; o[3][2] += p3*v4.z; o[3][3] += p3*v4.w;
        }
        __syncthreads();
    }

    // epilogue: normalize + write bf16 hi/lo directly (A operand for proj)
    #pragma unroll
    for (int i = 0; i < 4; i++) {
        int q = q0 + tr*4 + i;
        if (q >= NT) continue;
        float invl = (m_i[i] > -5e29f) ? (1.f / l_i[i]) : 0.f;
        float v0 = o[i][0]*invl, v1 = o[i][1]*invl, v2 = o[i][2]*invl, v3 = o[i][3]*invl;
        __nv_bfloat16 h0 = __float2bfloat16(v0); __nv_bfloat16 l0 = __float2bfloat16(v0 - __bfloat162float(h0));
        __nv_bfloat16 h1 = __float2bfloat16(v1); __nv_bfloat16 l1 = __float2bfloat16(v1 - __bfloat162float(h1));
        __nv_bfloat16 h2 = __float2bfloat16(v2); __nv_bfloat16 l2 = __float2bfloat16(v2 - __bfloat162float(h2));
        __nv_bfloat16 h3 = __float2bfloat16(v3); __nv_bfloat16 l3 = __float2bfloat16(v3 - __bfloat162float(h3));
        size_t idx = ((size_t)(b*NT) + q)*NC + h*ND + tc*4;
        uint2 hp, lp;
        hp.x = (uint32_t)__bfloat16_as_ushort(h0) | ((uint32_t)__bfloat16_as_ushort(h1) << 16);
        hp.y = (uint32_t)__bfloat16_as_ushort(h2) | ((uint32_t)__bfloat16_as_ushort(h3) << 16);
        lp.x = (uint32_t)__bfloat16_as_ushort(l0) | ((uint32_t)__bfloat16_as_ushort(l1) << 16);
        lp.y = (uint32_t)__bfloat16_as_ushort(l2) | ((uint32_t)__bfloat16_as_ushort(l3) << 16);
        *(uint2*)&g_xh[idx] = hp;
        *(uint2*)&g_xl[idx] = lp;
    }
}

// ---------------- launch -----------------------------------------------------
extern "C" void kernel_launch(void* const* d_in, const int* in_sizes, int n_in,
                              void* d_out, int out_size) {
    const float* x  = (const float*)d_in[0];
    const float* Wq = (const float*)d_in[1];
    const float* Wk = (const float*)d_in[2];
    const float* Wv = (const float*)d_in[3];
    const float* Wo = (const float*)d_in[4];
    const float* bo = (const float*)d_in[5];
    const int*   sv = (const int*)d_in[6];
    float* out = (float*)d_out;

    const int attn_smem = SMEM_FLOATS * (int)sizeof(float);
    cudaFuncSetAttribute((const void*)qkv_kernel,
                         cudaFuncAttributeMaxDynamicSharedMemorySize, SMEM_GEMM);
    cudaFuncSetAttribute((const void*)proj_kernel,
                         cudaFuncAttributeMaxDynamicSharedMemorySize, SMEM_GEMM);
    cudaFuncSetAttribute((const void*)attn_kernel,
                         cudaFuncAttributeMaxDynamicSharedMemorySize, attn_smem);

    cis_kernel<<<(NT*32 + 255)/256, 256>>>();

    const int cvt_bx = (NM*NC/4 + 255)/256;
    cvt_kernel<<<dim3(cvt_bx, 5), 256>>>(x, Wq, Wk, Wv, Wo);

    qkv_kernel<<<dim3(NC/BN, (NM + BM - 1)/BM, 3), 128, SMEM_GEMM>>>();
    attn_kernel<<<dim3((NT + 63)/64, NH, NB), 256, attn_smem>>>(sv);
    proj_kernel<<<dim3(NC/BN, (NM + BM - 1)/BM), 128, SMEM_GEMM>>>(bo, out);
}

// round 8
// speedup vs baseline: 1.8241x; 1.2040x over previous
#include <cuda_runtime.h>
#include <cuda_bf16.h>
#include <math.h>
#include <stdint.h>

#define NB 8
#define NT 1221
#define NC 1024
#define NH 16
#define ND 64
#define NM (NB*NT)      // 9768
#define HV 6
#define VTS 12
#define VTP 1280        // padded T for V^T layout (zero padding, 16B aligned rows)

#define BM 128
#define BN 64
#define KTILE 32
#define NKT (NC/KTILE)  // 32
#define PITCH 40        // GEMM smem pitch (bf16) -> conflict-free frags
#define APITCH 72       // attn smem pitch (bf16): 36 banks == 4 mod 32 -> conflict-free

// ---------------- scratch (device globals; no allocation allowed) ------------
__device__ float g_cs[NT*32];
__device__ float g_sn[NT*32];
__device__ __nv_bfloat16 g_xh[(size_t)NM*NC];   // A operand hi (X, later attn-out)
__device__ __nv_bfloat16 g_xl[(size_t)NM*NC];   // A operand lo
__device__ __nv_bfloat16 g_wh[4*(size_t)NC*NC]; // Wq,Wk,Wv,Wo hi
__device__ __nv_bfloat16 g_wl[4*(size_t)NC*NC]; // lo
__device__ __nv_bfloat16 g_qh[(size_t)NB*NH*NT*ND];  // Q hi [B,H,T,D]
__device__ __nv_bfloat16 g_ql[(size_t)NB*NH*NT*ND];
__device__ __nv_bfloat16 g_kh[(size_t)NB*NH*NT*ND];  // K hi [B,H,T,D]
__device__ __nv_bfloat16 g_kl[(size_t)NB*NH*NT*ND];
__device__ __nv_bfloat16 g_vth[(size_t)NB*NH*ND*VTP]; // V^T hi [B,H,D,VTP] (pad=0)
__device__ __nv_bfloat16 g_vtl[(size_t)NB*NH*ND*VTP];

// ---------------- helpers ----------------------------------------------------
__device__ __forceinline__ void mma16(float* d,
                                      uint32_t a0, uint32_t a1, uint32_t a2, uint32_t a3,
                                      uint32_t b0, uint32_t b1) {
    asm volatile(
        "mma.sync.aligned.m16n8k16.row.col.f32.bf16.bf16.f32 "
        "{%0,%1,%2,%3},{%4,%5,%6,%7},{%8,%9},{%0,%1,%2,%3};\n"
        : "+f"(d[0]), "+f"(d[1]), "+f"(d[2]), "+f"(d[3])
        : "r"(a0), "r"(a1), "r"(a2), "r"(a3), "r"(b0), "r"(b1));
}
__device__ __forceinline__ void cpa16(__nv_bfloat16* dst, const __nv_bfloat16* src, bool pred) {
    uint32_t d = (uint32_t)__cvta_generic_to_shared(dst);
    int sz = pred ? 16 : 0;
    asm volatile("cp.async.cg.shared.global [%0], [%1], 16, %2;\n"
                 :: "r"(d), "l"(src), "r"(sz));
}
#define CP_COMMIT() asm volatile("cp.async.commit_group;\n")

__device__ __forceinline__ void bf_split(float x, __nv_bfloat16& h, __nv_bfloat16& l) {
    h = __float2bfloat16(x);
    l = __float2bfloat16(x - __bfloat162float(h));
}
__device__ __forceinline__ uint32_t us2(__nv_bfloat16 a, __nv_bfloat16 b) {
    return (uint32_t)__bfloat16_as_ushort(a) | ((uint32_t)__bfloat16_as_ushort(b) << 16);
}

// GEMM smem layout (bf16 elements)
#define A_ELE (BM*PITCH)
#define B_ELE (BN*PITCH)
#define STAGE_ELE (2*A_ELE + 2*B_ELE)
#define AH_E(s) ((s)*STAGE_ELE)
#define AL_E(s) (AH_E(s) + A_ELE)
#define BH_E(s) (AH_E(s) + 2*A_ELE)
#define BL_E(s) (AH_E(s) + 2*A_ELE + B_ELE)
#define SMEM_GEMM (2*STAGE_ELE*2)

#define SMEM_ATTN (6*64*APITCH*2)  // 55296 B

// ---------------- rope table -------------------------------------------------
__global__ void cis_kernel() {
    int idx = blockIdx.x*256 + threadIdx.x;
    if (idx >= NT*32) return;
    int t = idx >> 5;
    int i = idx & 31;
    float inv = powf(10000.0f, -((float)(2*i) / 64.0f));
    float ang = (float)t * inv;
    float s, c;
    sincosf(ang, &s, &c);
    g_cs[idx] = c;
    g_sn[idx] = s;
}

// ---------------- fp32 -> (bf16 hi, bf16 lo) conversion ----------------------
__global__ __launch_bounds__(256) void cvt_kernel(
    const float* __restrict__ x,  const float* __restrict__ wq,
    const float* __restrict__ wk, const float* __restrict__ wv,
    const float* __restrict__ wo)
{
    const int seg = blockIdx.y;
    const float* src;
    __nv_bfloat16 *hi, *lo;
    size_t n;
    if (seg == 0) { src = x;  hi = g_xh; lo = g_xl; n = (size_t)NM*NC; }
    else {
        src = (seg==1) ? wq : (seg==2) ? wk : (seg==3) ? wv : wo;
        hi = g_wh + (size_t)(seg-1)*NC*NC;
        lo = g_wl + (size_t)(seg-1)*NC*NC;
        n = (size_t)NC*NC;
    }
    size_t i = ((size_t)blockIdx.x*256 + threadIdx.x) * 4;
    if (i >= n) return;
    float4 v = *(const float4*)(src + i);
    __nv_bfloat16 h0, l0, h1, l1, h2, l2, h3, l3;
    bf_split(v.x, h0, l0); bf_split(v.y, h1, l1);
    bf_split(v.z, h2, l2); bf_split(v.w, h3, l3);
    uint2 hp, lp;
    hp.x = us2(h0, h1); hp.y = us2(h2, h3);
    lp.x = us2(l0, l1); lp.y = us2(l2, l3);
    *(uint2*)(hi + i) = hp;
    *(uint2*)(lo + i) = lp;
}

// ---------------- 3-pass bf16-split GEMM mainloop (mma.m16n8k16) -------------
__device__ __forceinline__ void gemm_main(
    const __nv_bfloat16* __restrict__ Ah, const __nv_bfloat16* __restrict__ Al,
    const __nv_bfloat16* __restrict__ Bh, const __nv_bfloat16* __restrict__ Bl,
    int m0, int n0, __nv_bfloat16* sm, float acc[4][4][4])
{
    const int tid  = threadIdx.x;
    const int lane = tid & 31;
    const int warp = tid >> 5;
    const int wm = (warp >> 1) * 64;
    const int wn = (warp & 1) * 32;
    const int g = lane >> 2;
    const int t = lane & 3;

    const bool pa = (m0 + tid) < NM;
    const __nv_bfloat16* arh = Ah + (size_t)(m0 + tid) * NC;
    const __nv_bfloat16* arl = Al + (size_t)(m0 + tid) * NC;
    const int brr = tid >> 1;
    const int bc0 = (tid & 1) * 2;
    const __nv_bfloat16* brh = Bh + (size_t)(n0 + brr) * NC;
    const __nv_bfloat16* brl = Bl + (size_t)(n0 + brr) * NC;

    {
        __nv_bfloat16* dah = sm + AH_E(0) + tid*PITCH;
        __nv_bfloat16* dal = sm + AL_E(0) + tid*PITCH;
        #pragma unroll
        for (int c = 0; c < 4; c++) {
            cpa16(dah + c*8, arh + c*8, pa);
            cpa16(dal + c*8, arl + c*8, pa);
        }
        __nv_bfloat16* dbh = sm + BH_E(0) + brr*PITCH + bc0*8;
        __nv_bfloat16* dbl = sm + BL_E(0) + brr*PITCH + bc0*8;
        #pragma unroll
        for (int c = 0; c < 2; c++) {
            cpa16(dbh + c*8, brh + (bc0 + c)*8, true);
            cpa16(dbl + c*8, brl + (bc0 + c)*8, true);
        }
        CP_COMMIT();
    }

    for (int kt = 0; kt < NKT; kt++) {
        const int buf = kt & 1;
        if (kt + 1 < NKT) {
            const int k0n = (kt + 1) * KTILE;
            const int s2 = buf ^ 1;
            __nv_bfloat16* dah = sm + AH_E(s2) + tid*PITCH;
            __nv_bfloat16* dal = sm + AL_E(s2) + tid*PITCH;
            #pragma unroll
            for (int c = 0; c < 4; c++) {
                cpa16(dah + c*8, arh + k0n + c*8, pa);
                cpa16(dal + c*8, arl + k0n + c*8, pa);
            }
            __nv_bfloat16* dbh = sm + BH_E(s2) + brr*PITCH + bc0*8;
            __nv_bfloat16* dbl = sm + BL_E(s2) + brr*PITCH + bc0*8;
            #pragma unroll
            for (int c = 0; c < 2; c++) {
                cpa16(dbh + c*8, brh + k0n + (bc0 + c)*8, true);
                cpa16(dbl + c*8, brl + k0n + (bc0 + c)*8, true);
            }
            CP_COMMIT();
            asm volatile("cp.async.wait_group 1;\n" ::: "memory");
        } else {
            asm volatile("cp.async.wait_group 0;\n" ::: "memory");
        }
        __syncthreads();

        const __nv_bfloat16* tAh = sm + AH_E(buf);
        const __nv_bfloat16* tAl = sm + AL_E(buf);
        const __nv_bfloat16* tBh = sm + BH_E(buf);
        const __nv_bfloat16* tBl = sm + BL_E(buf);

        #pragma unroll
        for (int ks = 0; ks < 2; ks++) {
            const int kb = ks*16 + 2*t;
            uint32_t ah[4][4], al[4][4], bh[4][2], bl[4][2];
            #pragma unroll
            for (int mi = 0; mi < 4; mi++) {
                const int r0 = (wm + mi*16 + g) * PITCH;
                const int r1 = r0 + 8*PITCH;
                ah[mi][0] = *(const uint32_t*)&tAh[r0 + kb];
                ah[mi][1] = *(const uint32_t*)&tAh[r1 + kb];
                ah[mi][2] = *(const uint32_t*)&tAh[r0 + kb + 8];
                ah[mi][3] = *(const uint32_t*)&tAh[r1 + kb + 8];
                al[mi][0] = *(const uint32_t*)&tAl[r0 + kb];
                al[mi][1] = *(const uint32_t*)&tAl[r1 + kb];
                al[mi][2] = *(const uint32_t*)&tAl[r0 + kb + 8];
                al[mi][3] = *(const uint32_t*)&tAl[r1 + kb + 8];
            }
            #pragma unroll
            for (int ni = 0; ni < 4; ni++) {
                const int r = (wn + ni*8 + g) * PITCH;
                bh[ni][0] = *(const uint32_t*)&tBh[r + kb];
                bh[ni][1] = *(const uint32_t*)&tBh[r + kb + 8];
                bl[ni][0] = *(const uint32_t*)&tBl[r + kb];
                bl[ni][1] = *(const uint32_t*)&tBl[r + kb + 8];
            }
            #pragma unroll
            for (int mi = 0; mi < 4; mi++)
                #pragma unroll
                for (int ni = 0; ni < 4; ni++)
                    mma16(acc[mi][ni], ah[mi][0], ah[mi][1], ah[mi][2], ah[mi][3],
                          bh[ni][0], bh[ni][1]);
            #pragma unroll
            for (int mi = 0; mi < 4; mi++)
                #pragma unroll
                for (int ni = 0; ni < 4; ni++)
                    mma16(acc[mi][ni], al[mi][0], al[mi][1], al[mi][2], al[mi][3],
                          bh[ni][0], bh[ni][1]);
            #pragma unroll
            for (int mi = 0; mi < 4; mi++)
                #pragma unroll
                for (int ni = 0; ni < 4; ni++)
                    mma16(acc[mi][ni], ah[mi][0], ah[mi][1], ah[mi][2], ah[mi][3],
                          bl[ni][0], bl[ni][1]);
        }
        __syncthreads();
    }
}

// ---------------- fused QKV GEMM + RoPE + bf16 hi/lo outputs -----------------
__global__ __launch_bounds__(128, 3) void qkv_kernel()
{
    extern __shared__ __nv_bfloat16 sm[];
    const int which = blockIdx.z;
    const __nv_bfloat16* Bh = g_wh + (size_t)which*NC*NC;
    const __nv_bfloat16* Bl = g_wl + (size_t)which*NC*NC;

    const int m0 = blockIdx.y * BM;
    const int n0 = blockIdx.x * BN;

    float acc[4][4][4];
    #pragma unroll
    for (int mi = 0; mi < 4; mi++)
        #pragma unroll
        for (int ni = 0; ni < 4; ni++)
            #pragma unroll
            for (int j = 0; j < 4; j++) acc[mi][ni][j] = 0.f;

    gemm_main(g_xh, g_xl, Bh, Bl, m0, n0, sm, acc);

    const int tid  = threadIdx.x;
    const int lane = tid & 31;
    const int warp = tid >> 5;
    const int wm = (warp >> 1) * 64;
    const int wn = (warp & 1) * 32;
    const int g = lane >> 2;
    const int t = lane & 3;

    #pragma unroll
    for (int mi = 0; mi < 4; mi++) {
        #pragma unroll
        for (int half = 0; half < 2; half++) {
            const int m = m0 + wm + mi*16 + g + half*8;
            if (m >= NM) continue;
            const int bb  = m / NT;
            const int tok = m - bb*NT;
            #pragma unroll
            for (int ni = 0; ni < 4; ni++) {
                const int n = n0 + wn + ni*8 + 2*t;
                const int hh = n >> 6, d = n & 63;
                float e = acc[mi][ni][half*2 + 0];
                float o = acc[mi][ni][half*2 + 1];
                if (which < 2) {
                    float cv = g_cs[tok*32 + (d >> 1)];
                    float sv = g_sn[tok*32 + (d >> 1)];
                    float oe = e*cv - o*sv;
                    float oo = e*sv + o*cv;
                    __nv_bfloat16 he, le, ho, lo2;
                    bf_split(oe, he, le);
                    bf_split(oo, ho, lo2);
                    size_t idx = ((size_t)(bb*NH + hh)*NT + tok)*ND + d;
                    if (which == 0) {
                        *(uint32_t*)&g_qh[idx] = us2(he, ho);
                        *(uint32_t*)&g_ql[idx] = us2(le, lo2);
                    } else {
                        *(uint32_t*)&g_kh[idx] = us2(he, ho);
                        *(uint32_t*)&g_kl[idx] = us2(le, lo2);
                    }
                } else {
                    // V: store transposed [B,H,D,VTP] hi/lo
                    __nv_bfloat16 he, le, ho, lo2;
                    bf_split(e, he, le);
                    bf_split(o, ho, lo2);
                    size_t rbase = (size_t)(bb*NH + hh)*ND;
                    g_vth[(rbase + d  )*VTP + tok] = he;
                    g_vth[(rbase + d+1)*VTP + tok] = ho;
                    g_vtl[(rbase + d  )*VTP + tok] = le;
                    g_vtl[(rbase + d+1)*VTP + tok] = lo2;
                }
            }
        }
    }
}

// ---------------- output projection: out = AO @ Wo^T + bo --------------------
__global__ __launch_bounds__(128, 3) void proj_kernel(
    const float* __restrict__ bias, float* __restrict__ out)
{
    extern __shared__ __nv_bfloat16 sm[];
    const __nv_bfloat16* Bh = g_wh + (size_t)3*NC*NC;
    const __nv_bfloat16* Bl = g_wl + (size_t)3*NC*NC;

    const int m0 = blockIdx.y * BM;
    const int n0 = blockIdx.x * BN;

    float acc[4][4][4];
    #pragma unroll
    for (int mi = 0; mi < 4; mi++)
        #pragma unroll
        for (int ni = 0; ni < 4; ni++)
            #pragma unroll
            for (int j = 0; j < 4; j++) acc[mi][ni][j] = 0.f;

    gemm_main(g_xh, g_xl, Bh, Bl, m0, n0, sm, acc);

    const int tid  = threadIdx.x;
    const int lane = tid & 31;
    const int warp = tid >> 5;
    const int wm = (warp >> 1) * 64;
    const int wn = (warp & 1) * 32;
    const int g = lane >> 2;
    const int t = lane & 3;

    #pragma unroll
    for (int mi = 0; mi < 4; mi++) {
        #pragma unroll
        for (int half = 0; half < 2; half++) {
            const int m = m0 + wm + mi*16 + g + half*8;
            if (m >= NM) continue;
            #pragma unroll
            for (int ni = 0; ni < 4; ni++) {
                const int n = n0 + wn + ni*8 + 2*t;
                float2 r = make_float2(acc[mi][ni][half*2 + 0] + bias[n],
                                       acc[mi][ni][half*2 + 1] + bias[n+1]);
                *(float2*)&out[(size_t)m*NC + n] = r;
            }
        }
    }
}

// ---------------- tensor-core flash attention with modality mask -------------
__global__ __launch_bounds__(128, 2) void attn_kernel(const int* __restrict__ svp)
{
    extern __shared__ __nv_bfloat16 smb[];
    __nv_bfloat16* sQh = smb;
    __nv_bfloat16* sQl = smb + 64*APITCH;
    __nv_bfloat16* sKh = smb + 2*64*APITCH;
    __nv_bfloat16* sKl = smb + 3*64*APITCH;
    __nv_bfloat16* sVh = smb + 4*64*APITCH;
    __nv_bfloat16* sVl = smb + 5*64*APITCH;

    const int S_V = *svp;
    const int qt = blockIdx.x, h = blockIdx.y, b = blockIdx.z;
    const int hc = (h < HV) ? 0 : ((h < VTS) ? 1 : 2);
    const int q0 = qt * 64;
    const int tid = threadIdx.x, lane = tid & 31, w = tid >> 5;
    const int g = lane >> 2, t = lane & 3;
    const size_t bh = (size_t)(b*NH + h);

    // ---- load Q tile (hi/lo) ----
    {
        int r = tid >> 1, hf = tid & 1;
        int q = q0 + r;
        uint4 z = make_uint4(0,0,0,0);
        const uint4* srh = (const uint4*)&g_qh[(bh*NT + (q < NT ? q : 0))*ND + hf*32];
        const uint4* srl = (const uint4*)&g_ql[(bh*NT + (q < NT ? q : 0))*ND + hf*32];
        #pragma unroll
        for (int i = 0; i < 4; i++) {
            uint4 vh_ = (q < NT) ? srh[i] : z;
            uint4 vl_ = (q < NT) ? srl[i] : z;
            *(uint4*)&sQh[r*APITCH + hf*32 + i*8] = vh_;
            *(uint4*)&sQl[r*APITCH + hf*32 + i*8] = vl_;
        }
    }
    __syncthreads();

    // ---- Q fragments (resident across KV loop) ----
    uint32_t qfh[4][4], qfl[4][4];
    {
        const int r0 = (w*16 + g)*APITCH, r1 = r0 + 8*APITCH;
        #pragma unroll
        for (int ks = 0; ks < 4; ks++) {
            const int kb = ks*16 + 2*t;
            qfh[ks][0] = *(const uint32_t*)&sQh[r0 + kb];
            qfh[ks][1] = *(const uint32_t*)&sQh[r1 + kb];
            qfh[ks][2] = *(const uint32_t*)&sQh[r0 + kb + 8];
            qfh[ks][3] = *(const uint32_t*)&sQh[r1 + kb + 8];
            qfl[ks][0] = *(const uint32_t*)&sQl[r0 + kb];
            qfl[ks][1] = *(const uint32_t*)&sQl[r1 + kb];
            qfl[ks][2] = *(const uint32_t*)&sQl[r0 + kb + 8];
            qfl[ks][3] = *(const uint32_t*)&sQl[r1 + kb + 8];
        }
    }

    float O[8][4];
    #pragma unroll
    for (int ni = 0; ni < 8; ni++)
        #pragma unroll
        for (int c = 0; c < 4; c++) O[ni][c] = 0.f;
    float m_[2] = {-1e30f, -1e30f}, l_[2] = {0.f, 0.f};

    const int ceil_sv = (S_V + 63) >> 6;
    int kv_lo = 0, kv_hi = 0;
    if (hc == 0)      { if (q0 < S_V) { kv_lo = 0; kv_hi = ceil_sv; } }
    else if (hc == 1) { if (q0 + 63 >= S_V) { kv_lo = S_V >> 6; kv_hi = qt + 1; } }
    else              { kv_lo = 0; kv_hi = (qt + 1 > ceil_sv) ? (qt + 1) : ceil_sv; }

    const int qg = q0 + w*16 + g;

    for (int kvt = kv_lo; kvt < kv_hi; kvt++) {
        const int kv0 = kvt * 64;
        __syncthreads();
        // ---- load K tile (rows kv) + V^T tile (rows d) ----
        {
            int r = tid >> 1, hf = tid & 1;
            int kv = kv0 + r;
            uint4 z = make_uint4(0,0,0,0);
            const uint4* kh_ = (const uint4*)&g_kh[(bh*NT + (kv < NT ? kv : 0))*ND + hf*32];
            const uint4* kl_ = (const uint4*)&g_kl[(bh*NT + (kv < NT ? kv : 0))*ND + hf*32];
            const uint4* vh_ = (const uint4*)&g_vth[(bh*ND + r)*VTP + kv0 + hf*32];
            const uint4* vl_ = (const uint4*)&g_vtl[(bh*ND + r)*VTP + kv0 + hf*32];
            #pragma unroll
            for (int i = 0; i < 4; i++) {
                uint4 a = (kv < NT) ? kh_[i] : z;
                uint4 c = (kv < NT) ? kl_[i] : z;
                *(uint4*)&sKh[r*APITCH + hf*32 + i*8] = a;
                *(uint4*)&sKl[r*APITCH + hf*32 + i*8] = c;
                uint4 d0 = vh_[i];
                uint4 d1 = vl_[i];
                *(uint4*)&sVh[r*APITCH + hf*32 + i*8] = d0;
                *(uint4*)&sVl[r*APITCH + hf*32 + i*8] = d1;
            }
        }
        __syncthreads();

        // ---- S = Q K^T (3-pass split) ----
        float sa[8][4];
        #pragma unroll
        for (int ni = 0; ni < 8; ni++)
            #pragma unroll
            for (int c = 0; c < 4; c++) sa[ni][c] = 0.f;

        #pragma unroll
        for (int ks = 0; ks < 4; ks++) {
            const int kb = ks*16 + 2*t;
            uint32_t bhf[8][2], blf[8][2];
            #pragma unroll
            for (int ni = 0; ni < 8; ni++) {
                const int rr = (ni*8 + g)*APITCH;
                bhf[ni][0] = *(const uint32_t*)&sKh[rr + kb];
                bhf[ni][1] = *(const uint32_t*)&sKh[rr + kb + 8];
                blf[ni][0] = *(const uint32_t*)&sKl[rr + kb];
                blf[ni][1] = *(const uint32_t*)&sKl[rr + kb + 8];
            }
            #pragma unroll
            for (int ni = 0; ni < 8; ni++)
                mma16(sa[ni], qfh[ks][0], qfh[ks][1], qfh[ks][2], qfh[ks][3],
                      bhf[ni][0], bhf[ni][1]);
            #pragma unroll
            for (int ni = 0; ni < 8; ni++)
                mma16(sa[ni], qfl[ks][0], qfl[ks][1], qfl[ks][2], qfl[ks][3],
                      bhf[ni][0], bhf[ni][1]);
            #pragma unroll
            for (int ni = 0; ni < 8; ni++)
                mma16(sa[ni], qfh[ks][0], qfh[ks][1], qfh[ks][2], qfh[ks][3],
                      blf[ni][0], blf[ni][1]);
        }

        // ---- mask + scale ----
        #pragma unroll
        for (int ni = 0; ni < 8; ni++) {
            #pragma unroll
            for (int c = 0; c < 4; c++) {
                const int qq = qg + ((c >= 2) ? 8 : 0);
                const int kv = kv0 + ni*8 + 2*t + (c & 1);
                bool ok;
                if (hc == 0)      ok = (qq < S_V) && (kv < S_V);
                else if (hc == 1) ok = (qq >= S_V) && (kv >= S_V) && (qq >= kv);
                else              ok = (kv < S_V) || (qq >= kv);
                ok = ok && (kv < NT) && (qq < NT);
                sa[ni][c] = ok ? sa[ni][c] * 0.125f : -1e30f;
            }
        }

        // ---- online softmax (rows g, g+8; quad-shfl reductions) ----
        #pragma unroll
        for (int row = 0; row < 2; row++) {
            float rm = -1e30f;
            #pragma unroll
            for (int ni = 0; ni < 8; ni++)
                rm = fmaxf(rm, fmaxf(sa[ni][row*2], sa[ni][row*2+1]));
            rm = fmaxf(rm, __shfl_xor_sync(0xffffffffu, rm, 1));
            rm = fmaxf(rm, __shfl_xor_sync(0xffffffffu, rm, 2));
            float mnew = fmaxf(m_[row], rm);
            float alpha = __expf(m_[row] - mnew);
            m_[row] = mnew;
            float psum = 0.f;
            #pragma unroll
            for (int ni = 0; ni < 8; ni++) {
                float p0 = __expf(sa[ni][row*2]   - mnew);
                float p1 = __expf(sa[ni][row*2+1] - mnew);
                sa[ni][row*2]   = p0;
                sa[ni][row*2+1] = p1;
                psum += p0 + p1;
            }
            psum += __shfl_xor_sync(0xffffffffu, psum, 1);
            psum += __shfl_xor_sync(0xffffffffu, psum, 2);
            l_[row] = l_[row]*alpha + psum;
            #pragma unroll
            for (int ni = 0; ni < 8; ni++) {
                O[ni][row*2]   *= alpha;
                O[ni][row*2+1] *= alpha;
            }
        }

        // ---- P -> A fragments (hi/lo) in registers ----
        uint32_t pfh[4][4], pfl[4][4];
        #pragma unroll
        for (int j = 0; j < 4; j++) {
            __nv_bfloat16 h0, l0, h1, l1;
            bf_split(sa[2*j][0], h0, l0); bf_split(sa[2*j][1], h1, l1);
            pfh[j][0] = us2(h0, h1); pfl[j][0] = us2(l0, l1);
            bf_split(sa[2*j][2], h0, l0); bf_split(sa[2*j][3], h1, l1);
            pfh[j][1] = us2(h0, h1); pfl[j][1] = us2(l0, l1);
            bf_split(sa[2*j+1][0], h0, l0); bf_split(sa[2*j+1][1], h1, l1);
            pfh[j][2] = us2(h0, h1); pfl[j][2] = us2(l0, l1);
            bf_split(sa[2*j+1][2], h0, l0); bf_split(sa[2*j+1][3], h1, l1);
            pfh[j][3] = us2(h0, h1); pfl[j][3] = us2(l0, l1);
        }

        // ---- O += P V (3-pass split) ----
        #pragma unroll
        for (int j = 0; j < 4; j++) {
            const int kb = j*16 + 2*t;
            uint32_t vhf[8][2], vlf[8][2];
            #pragma unroll
            for (int ni = 0; ni < 8; ni++) {
                const int rr = (ni*8 + g)*APITCH;
                vhf[ni][0] = *(const uint32_t*)&sVh[rr + kb];
                vhf[ni][1] = *(const uint32_t*)&sVh[rr + kb + 8];
                vlf[ni][0] = *(const uint32_t*)&sVl[rr + kb];
                vlf[ni][1] = *(const uint32_t*)&sVl[rr + kb + 8];
            }
            #pragma unroll
            for (int ni = 0; ni < 8; ni++)
                mma16(O[ni], pfh[j][0], pfh[j][1], pfh[j][2], pfh[j][3],
                      vhf[ni][0], vhf[ni][1]);
            #pragma unroll
            for (int ni = 0; ni < 8; ni++)
                mma16(O[ni], pfl[j][0], pfl[j][1], pfl[j][2], pfl[j][3],
                      vhf[ni][0], vhf[ni][1]);
            #pragma unroll
            for (int ni = 0; ni < 8; ni++)
                mma16(O[ni], pfh[j][0], pfh[j][1], pfh[j][2], pfh[j][3],
                      vlf[ni][0], vlf[ni][1]);
        }
    }

    // ---- epilogue: normalize + write bf16 hi/lo (A operand for proj) ----
    #pragma unroll
    for (int row = 0; row < 2; row++) {
        const int q = q0 + w*16 + g + row*8;
        if (q >= NT) continue;
        const float invl = (m_[row] > -5e29f) ? (1.f / l_[row]) : 0.f;
        const size_t base = ((size_t)(b*NT) + q)*NC + h*ND;
        #pragma unroll
        for (int ni = 0; ni < 8; ni++) {
            float x0 = O[ni][row*2]   * invl;
            float x1 = O[ni][row*2+1] * invl;
            __nv_bfloat16 h0, l0, h1, l1;
            bf_split(x0, h0, l0);
            bf_split(x1, h1, l1);
            *(uint32_t*)&g_xh[base + ni*8 + 2*t] = us2(h0, h1);
            *(uint32_t*)&g_xl[base + ni*8 + 2*t] = us2(l0, l1);
        }
    }
}

// ---------------- launch -----------------------------------------------------
extern "C" void kernel_launch(void* const* d_in, const int* in_sizes, int n_in,
                              void* d_out, int out_size) {
    const float* x  = (const float*)d_in[0];
    const float* Wq = (const float*)d_in[1];
    const float* Wk = (const float*)d_in[2];
    const float* Wv = (const float*)d_in[3];
    const float* Wo = (const float*)d_in[4];
    const float* bo = (const float*)d_in[5];
    const int*   sv = (const int*)d_in[6];
    float* out = (float*)d_out;

    cudaFuncSetAttribute((const void*)qkv_kernel,
                         cudaFuncAttributeMaxDynamicSharedMemorySize, SMEM_GEMM);
    cudaFuncSetAttribute((const void*)proj_kernel,
                         cudaFuncAttributeMaxDynamicSharedMemorySize, SMEM_GEMM);
    cudaFuncSetAttribute((const void*)attn_kernel,
                         cudaFuncAttributeMaxDynamicSharedMemorySize, SMEM_ATTN);

    cis_kernel<<<(NT*32 + 255)/256, 256>>>();

    const int cvt_bx = (NM*NC/4 + 255)/256;
    cvt_kernel<<<dim3(cvt_bx, 5), 256>>>(x, Wq, Wk, Wv, Wo);

    qkv_kernel<<<dim3(NC/BN, (NM + BM - 1)/BM, 3), 128, SMEM_GEMM>>>();
    attn_kernel<<<dim3((NT + 63)/64, NH, NB), 128, SMEM_ATTN>>>(sv);
    proj_kernel<<<dim3(NC/BN, (NM + BM - 1)/BM), 128, SMEM_GEMM>>>(bo, out);
}

// round 10
// speedup vs baseline: 1.9667x; 1.0782x over previous
#include <cuda_runtime.h>
#include <cuda_bf16.h>
#include <math.h>
#include <stdint.h>

#define NB 8
#define NT 1221
#define NC 1024
#define NH 16
#define ND 64
#define NM (NB*NT)      // 9768
#define HV 6
#define VTS 12
#define VTP 1280        // padded T for V^T layout (zero padding, 16B aligned rows)

#define BM 128
#define BN 64
#define KTILE 32
#define NKT (NC/KTILE)  // 32
#define PITCH 40        // GEMM smem pitch (bf16) -> conflict-free ldmatrix
#define APITCH 72       // attn smem pitch (bf16) -> conflict-free ldmatrix

// ---------------- scratch (device globals; no allocation allowed) ------------
__device__ float g_cs[NT*32];
__device__ float g_sn[NT*32];
__device__ __nv_bfloat16 g_xh[(size_t)NM*NC];   // A operand hi (X, later attn-out)
__device__ __nv_bfloat16 g_xl[(size_t)NM*NC];   // A operand lo
__device__ __nv_bfloat16 g_wh[4*(size_t)NC*NC]; // Wq,Wk,Wv,Wo hi
__device__ __nv_bfloat16 g_wl[4*(size_t)NC*NC]; // lo
__device__ __nv_bfloat16 g_qh[(size_t)NB*NH*NT*ND];  // Q hi [B,H,T,D]
__device__ __nv_bfloat16 g_ql[(size_t)NB*NH*NT*ND];
__device__ __nv_bfloat16 g_kh[(size_t)NB*NH*NT*ND];  // K hi [B,H,T,D]
__device__ __nv_bfloat16 g_kl[(size_t)NB*NH*NT*ND];
__device__ __nv_bfloat16 g_vth[(size_t)NB*NH*ND*VTP]; // V^T hi [B,H,D,VTP] (pad=0)
__device__ __nv_bfloat16 g_vtl[(size_t)NB*NH*ND*VTP];

// ---------------- helpers ----------------------------------------------------
__device__ __forceinline__ void mma16(float* d,
                                      uint32_t a0, uint32_t a1, uint32_t a2, uint32_t a3,
                                      uint32_t b0, uint32_t b1) {
    asm volatile(
        "mma.sync.aligned.m16n8k16.row.col.f32.bf16.bf16.f32 "
        "{%0,%1,%2,%3},{%4,%5,%6,%7},{%8,%9},{%0,%1,%2,%3};\n"
        : "+f"(d[0]), "+f"(d[1]), "+f"(d[2]), "+f"(d[3])
        : "r"(a0), "r"(a1), "r"(a2), "r"(a3), "r"(b0), "r"(b1));
}
__device__ __forceinline__ void ldsm4(uint32_t& r0, uint32_t& r1, uint32_t& r2, uint32_t& r3,
                                      uint32_t addr) {
    asm volatile("ldmatrix.sync.aligned.m8n8.x4.shared.b16 {%0,%1,%2,%3}, [%4];"
                 : "=r"(r0), "=r"(r1), "=r"(r2), "=r"(r3) : "r"(addr));
}
__device__ __forceinline__ void cpa16(__nv_bfloat16* dst, const __nv_bfloat16* src, bool pred) {
    uint32_t d = (uint32_t)__cvta_generic_to_shared(dst);
    int sz = pred ? 16 : 0;
    asm volatile("cp.async.cg.shared.global [%0], [%1], 16, %2;\n"
                 :: "r"(d), "l"(src), "r"(sz));
}
#define CP_COMMIT() asm volatile("cp.async.commit_group;\n")

__device__ __forceinline__ void bf_split(float x, __nv_bfloat16& h, __nv_bfloat16& l) {
    h = __float2bfloat16(x);
    l = __float2bfloat16(x - __bfloat162float(h));
}
__device__ __forceinline__ uint32_t us2(__nv_bfloat16 a, __nv_bfloat16 b) {
    return (uint32_t)__bfloat16_as_ushort(a) | ((uint32_t)__bfloat16_as_ushort(b) << 16);
}

// GEMM smem layout (bf16 elements)
#define A_ELE (BM*PITCH)
#define B_ELE (BN*PITCH)
#define STAGE_ELE (2*A_ELE + 2*B_ELE)
#define AH_E(s) ((s)*STAGE_ELE)
#define AL_E(s) (AH_E(s) + A_ELE)
#define BH_E(s) (AH_E(s) + 2*A_ELE)
#define BL_E(s) (AH_E(s) + 2*A_ELE + B_ELE)
#define SMEM_GEMM (2*STAGE_ELE*2)

#define SMEM_ATTN (6*64*APITCH*2)  // 55296 B

// ---------------- rope table -------------------------------------------------
__global__ void cis_kernel() {
    int idx = blockIdx.x*256 + threadIdx.x;
    if (idx >= NT*32) return;
    int t = idx >> 5;
    int i = idx & 31;
    float inv = powf(10000.0f, -((float)(2*i) / 64.0f));
    float ang = (float)t * inv;
    float s, c;
    sincosf(ang, &s, &c);
    g_cs[idx] = c;
    g_sn[idx] = s;
}

// ---------------- fp32 -> (bf16 hi, bf16 lo) conversion ----------------------
__global__ __launch_bounds__(256) void cvt_kernel(
    const float* __restrict__ x,  const float* __restrict__ wq,
    const float* __restrict__ wk, const float* __restrict__ wv,
    const float* __restrict__ wo)
{
    const int seg = blockIdx.y;
    const float* src;
    __nv_bfloat16 *hi, *lo;
    size_t n;
    if (seg == 0) { src = x;  hi = g_xh; lo = g_xl; n = (size_t)NM*NC; }
    else {
        src = (seg==1) ? wq : (seg==2) ? wk : (seg==3) ? wv : wo;
        hi = g_wh + (size_t)(seg-1)*NC*NC;
        lo = g_wl + (size_t)(seg-1)*NC*NC;
        n = (size_t)NC*NC;
    }
    size_t i = ((size_t)blockIdx.x*256 + threadIdx.x) * 4;
    if (i >= n) return;
    float4 v = *(const float4*)(src + i);
    __nv_bfloat16 h0, l0, h1, l1, h2, l2, h3, l3;
    bf_split(v.x, h0, l0); bf_split(v.y, h1, l1);
    bf_split(v.z, h2, l2); bf_split(v.w, h3, l3);
    uint2 hp, lp;
    hp.x = us2(h0, h1); hp.y = us2(h2, h3);
    lp.x = us2(l0, l1); lp.y = us2(l2, l3);
    *(uint2*)(hi + i) = hp;
    *(uint2*)(lo + i) = lp;
}

// ---------------- 3-pass bf16-split GEMM mainloop (mma + ldmatrix) -----------
__device__ __forceinline__ void gemm_main(
    const __nv_bfloat16* __restrict__ Ah, const __nv_bfloat16* __restrict__ Al,
    const __nv_bfloat16* __restrict__ Bh, const __nv_bfloat16* __restrict__ Bl,
    int m0, int n0, __nv_bfloat16* sm, float acc[4][4][4])
{
    const int tid  = threadIdx.x;
    const int lane = tid & 31;
    const int warp = tid >> 5;
    const int wm = (warp >> 1) * 64;
    const int wn = (warp & 1) * 32;

    // ldmatrix lane->row/col mapping (A-style: m0..3 = {r0-7,k0}{r8-15,k0}{r0-7,k8}{r8-15,k8})
    const int lrowA = (lane & 7) + ((lane >> 3) & 1) * 8;
    const int lcolA = ((lane >> 4) & 1) * 8;
    // B-style: m0..3 = {n0-7,k0}{n0-7,k8}{n8-15,k0}{n8-15,k8}
    const int lrowB = (lane & 7) + ((lane >> 4) & 1) * 8;
    const int lcolB = ((lane >> 3) & 1) * 8;

    const uint32_t sb = (uint32_t)__cvta_generic_to_shared(sm);

    const bool pa = (m0 + tid) < NM;
    const __nv_bfloat16* arh = Ah + (size_t)(m0 + tid) * NC;
    const __nv_bfloat16* arl = Al + (size_t)(m0 + tid) * NC;
    const int brr = tid >> 1;
    const int bc0 = (tid & 1) * 2;
    const __nv_bfloat16* brh = Bh + (size_t)(n0 + brr) * NC;
    const __nv_bfloat16* brl = Bl + (size_t)(n0 + brr) * NC;

    {
        __nv_bfloat16* dah = sm + AH_E(0) + tid*PITCH;
        __nv_bfloat16* dal = sm + AL_E(0) + tid*PITCH;
        #pragma unroll
        for (int c = 0; c < 4; c++) {
            cpa16(dah + c*8, arh + c*8, pa);
            cpa16(dal + c*8, arl + c*8, pa);
        }
        __nv_bfloat16* dbh = sm + BH_E(0) + brr*PITCH + bc0*8;
        __nv_bfloat16* dbl = sm + BL_E(0) + brr*PITCH + bc0*8;
        #pragma unroll
        for (int c = 0; c < 2; c++) {
            cpa16(dbh + c*8, brh + (bc0 + c)*8, true);
            cpa16(dbl + c*8, brl + (bc0 + c)*8, true);
        }
        CP_COMMIT();
    }

    for (int kt = 0; kt < NKT; kt++) {
        const int buf = kt & 1;
        if (kt + 1 < NKT) {
            const int k0n = (kt + 1) * KTILE;
            const int s2 = buf ^ 1;
            __nv_bfloat16* dah = sm + AH_E(s2) + tid*PITCH;
            __nv_bfloat16* dal = sm + AL_E(s2) + tid*PITCH;
            #pragma unroll
            for (int c = 0; c < 4; c++) {
                cpa16(dah + c*8, arh + k0n + c*8, pa);
                cpa16(dal + c*8, arl + k0n + c*8, pa);
            }
            __nv_bfloat16* dbh = sm + BH_E(s2) + brr*PITCH + bc0*8;
            __nv_bfloat16* dbl = sm + BL_E(s2) + brr*PITCH + bc0*8;
            #pragma unroll
            for (int c = 0; c < 2; c++) {
                cpa16(dbh + c*8, brh + k0n + (bc0 + c)*8, true);
                cpa16(dbl + c*8, brl + k0n + (bc0 + c)*8, true);
            }
            CP_COMMIT();
            asm volatile("cp.async.wait_group 1;\n" ::: "memory");
        } else {
            asm volatile("cp.async.wait_group 0;\n" ::: "memory");
        }
        __syncthreads();

        const uint32_t aBh = sb + (uint32_t)(AH_E(buf) + (wm + lrowA)*PITCH + lcolA)*2;
        const uint32_t aBl = sb + (uint32_t)(AL_E(buf) + (wm + lrowA)*PITCH + lcolA)*2;
        const uint32_t bBh = sb + (uint32_t)(BH_E(buf) + (wn + lrowB)*PITCH + lcolB)*2;
        const uint32_t bBl = sb + (uint32_t)(BL_E(buf) + (wn + lrowB)*PITCH + lcolB)*2;

        #pragma unroll
        for (int ks = 0; ks < 2; ks++) {
            const uint32_t ko = (uint32_t)(ks*16*2);
            uint32_t ah[4][4], al[4][4], bh[4][2], bl[4][2];
            #pragma unroll
            for (int mi = 0; mi < 4; mi++) {
                ldsm4(ah[mi][0], ah[mi][1], ah[mi][2], ah[mi][3],
                      aBh + (uint32_t)(mi*16*PITCH*2) + ko);
                ldsm4(al[mi][0], al[mi][1], al[mi][2], al[mi][3],
                      aBl + (uint32_t)(mi*16*PITCH*2) + ko);
            }
            #pragma unroll
            for (int np = 0; np < 2; np++) {
                ldsm4(bh[2*np][0], bh[2*np][1], bh[2*np+1][0], bh[2*np+1][1],
                      bBh + (uint32_t)(np*16*PITCH*2) + ko);
                ldsm4(bl[2*np][0], bl[2*np][1], bl[2*np+1][0], bl[2*np+1][1],
                      bBl + (uint32_t)(np*16*PITCH*2) + ko);
            }
            #pragma unroll
            for (int mi = 0; mi < 4; mi++)
                #pragma unroll
                for (int ni = 0; ni < 4; ni++)
                    mma16(acc[mi][ni], ah[mi][0], ah[mi][1], ah[mi][2], ah[mi][3],
                          bh[ni][0], bh[ni][1]);
            #pragma unroll
            for (int mi = 0; mi < 4; mi++)
                #pragma unroll
                for (int ni = 0; ni < 4; ni++)
                    mma16(acc[mi][ni], al[mi][0], al[mi][1], al[mi][2], al[mi][3],
                          bh[ni][0], bh[ni][1]);
            #pragma unroll
            for (int mi = 0; mi < 4; mi++)
                #pragma unroll
                for (int ni = 0; ni < 4; ni++)
                    mma16(acc[mi][ni], ah[mi][0], ah[mi][1], ah[mi][2], ah[mi][3],
                          bl[ni][0], bl[ni][1]);
        }
        __syncthreads();
    }
}

// ---------------- fused QKV GEMM + RoPE + bf16 hi/lo outputs -----------------
__global__ __launch_bounds__(128, 3) void qkv_kernel()
{
    extern __shared__ __nv_bfloat16 sm[];
    const int which = blockIdx.z;
    const __nv_bfloat16* Bh = g_wh + (size_t)which*NC*NC;
    const __nv_bfloat16* Bl = g_wl + (size_t)which*NC*NC;

    const int m0 = blockIdx.y * BM;
    const int n0 = blockIdx.x * BN;

    float acc[4][4][4];
    #pragma unroll
    for (int mi = 0; mi < 4; mi++)
        #pragma unroll
        for (int ni = 0; ni < 4; ni++)
            #pragma unroll
            for (int j = 0; j < 4; j++) acc[mi][ni][j] = 0.f;

    gemm_main(g_xh, g_xl, Bh, Bl, m0, n0, sm, acc);

    const int tid  = threadIdx.x;
    const int lane = tid & 31;
    const int warp = tid >> 5;
    const int wm = (warp >> 1) * 64;
    const int wn = (warp & 1) * 32;
    const int g = lane >> 2;
    const int t = lane & 3;

    #pragma unroll
    for (int mi = 0; mi < 4; mi++) {
        #pragma unroll
        for (int half = 0; half < 2; half++) {
            const int m = m0 + wm + mi*16 + g + half*8;
            if (m >= NM) continue;
            const int bb  = m / NT;
            const int tok = m - bb*NT;
            #pragma unroll
            for (int ni = 0; ni < 4; ni++) {
                const int n = n0 + wn + ni*8 + 2*t;
                const int hh = n >> 6, d = n & 63;
                float e = acc[mi][ni][half*2 + 0];
                float o = acc[mi][ni][half*2 + 1];
                if (which < 2) {
                    float cv = g_cs[tok*32 + (d >> 1)];
                    float sv = g_sn[tok*32 + (d >> 1)];
                    float oe = e*cv - o*sv;
                    float oo = e*sv + o*cv;
                    __nv_bfloat16 he, le, ho, lo2;
                    bf_split(oe, he, le);
                    bf_split(oo, ho, lo2);
                    size_t idx = ((size_t)(bb*NH + hh)*NT + tok)*ND + d;
                    if (which == 0) {
                        *(uint32_t*)&g_qh[idx] = us2(he, ho);
                        *(uint32_t*)&g_ql[idx] = us2(le, lo2);
                    } else {
                        *(uint32_t*)&g_kh[idx] = us2(he, ho);
                        *(uint32_t*)&g_kl[idx] = us2(le, lo2);
                    }
                } else {
                    __nv_bfloat16 he, le, ho, lo2;
                    bf_split(e, he, le);
                    bf_split(o, ho, lo2);
                    size_t rbase = (size_t)(bb*NH + hh)*ND;
                    g_vth[(rbase + d  )*VTP + tok] = he;
                    g_vth[(rbase + d+1)*VTP + tok] = ho;
                    g_vtl[(rbase + d  )*VTP + tok] = le;
                    g_vtl[(rbase + d+1)*VTP + tok] = lo2;
                }
            }
        }
    }
}

// ---------------- output projection: out = AO @ Wo^T + bo --------------------
__global__ __launch_bounds__(128, 3) void proj_kernel(
    const float* __restrict__ bias, float* __restrict__ out)
{
    extern __shared__ __nv_bfloat16 sm[];
    const __nv_bfloat16* Bh = g_wh + (size_t)3*NC*NC;
    const __nv_bfloat16* Bl = g_wl + (size_t)3*NC*NC;

    const int m0 = blockIdx.y * BM;
    const int n0 = blockIdx.x * BN;

    float acc[4][4][4];
    #pragma unroll
    for (int mi = 0; mi < 4; mi++)
        #pragma unroll
        for (int ni = 0; ni < 4; ni++)
            #pragma unroll
            for (int j = 0; j < 4; j++) acc[mi][ni][j] = 0.f;

    gemm_main(g_xh, g_xl, Bh, Bl, m0, n0, sm, acc);

    const int tid  = threadIdx.x;
    const int lane = tid & 31;
    const int warp = tid >> 5;
    const int wm = (warp >> 1) * 64;
    const int wn = (warp & 1) * 32;
    const int g = lane >> 2;
    const int t = lane & 3;

    #pragma unroll
    for (int mi = 0; mi < 4; mi++) {
        #pragma unroll
        for (int half = 0; half < 2; half++) {
            const int m = m0 + wm + mi*16 + g + half*8;
            if (m >= NM) continue;
            #pragma unroll
            for (int ni = 0; ni < 4; ni++) {
                const int n = n0 + wn + ni*8 + 2*t;
                float2 r = make_float2(acc[mi][ni][half*2 + 0] + bias[n],
                                       acc[mi][ni][half*2 + 1] + bias[n+1]);
                *(float2*)&out[(size_t)m*NC + n] = r;
            }
        }
    }
}

// ---------------- tensor-core flash attention with modality mask -------------
__global__ __launch_bounds__(128, 2) void attn_kernel(const int* __restrict__ svp)
{
    extern __shared__ __nv_bfloat16 smb[];
    __nv_bfloat16* sQh = smb;
    __nv_bfloat16* sQl = smb + 64*APITCH;
    __nv_bfloat16* sKh = smb + 2*64*APITCH;
    __nv_bfloat16* sKl = smb + 3*64*APITCH;
    __nv_bfloat16* sVh = smb + 4*64*APITCH;
    __nv_bfloat16* sVl = smb + 5*64*APITCH;

    const int S_V = *svp;
    const int qt = blockIdx.x, h = blockIdx.y, b = blockIdx.z;
    const int hc = (h < HV) ? 0 : ((h < VTS) ? 1 : 2);
    const int q0 = qt * 64;
    const int tid = threadIdx.x, lane = tid & 31, w = tid >> 5;
    const int g = lane >> 2, t = lane & 3;
    const size_t bh = (size_t)(b*NH + h);

    const int lrowA = (lane & 7) + ((lane >> 3) & 1) * 8;
    const int lcolA = ((lane >> 4) & 1) * 8;
    const int lrowB = (lane & 7) + ((lane >> 4) & 1) * 8;
    const int lcolB = ((lane >> 3) & 1) * 8;

    const uint32_t sbQh = (uint32_t)__cvta_generic_to_shared(sQh);
    const uint32_t sbQl = (uint32_t)__cvta_generic_to_shared(sQl);
    const uint32_t sbKh = (uint32_t)__cvta_generic_to_shared(sKh);
    const uint32_t sbKl = (uint32_t)__cvta_generic_to_shared(sKl);
    const uint32_t sbVh = (uint32_t)__cvta_generic_to_shared(sVh);
    const uint32_t sbVl = (uint32_t)__cvta_generic_to_shared(sVl);

    // ---- load Q tile (hi/lo) ----
    {
        int r = tid >> 1, hf = tid & 1;
        int q = q0 + r;
        uint4 z = make_uint4(0,0,0,0);
        const uint4* srh = (const uint4*)&g_qh[(bh*NT + (q < NT ? q : 0))*ND + hf*32];
        const uint4* srl = (const uint4*)&g_ql[(bh*NT + (q < NT ? q : 0))*ND + hf*32];
        #pragma unroll
        for (int i = 0; i < 4; i++) {
            uint4 vh_ = (q < NT) ? srh[i] : z;
            uint4 vl_ = (q < NT) ? srl[i] : z;
            *(uint4*)&sQh[r*APITCH + hf*32 + i*8] = vh_;
            *(uint4*)&sQl[r*APITCH + hf*32 + i*8] = vl_;
        }
    }
    __syncthreads();

    // ---- Q fragments (resident across KV loop) via ldmatrix ----
    uint32_t qfh[4][4], qfl[4][4];
    {
        const uint32_t qb = (uint32_t)(((w*16 + lrowA)*APITCH + lcolA)*2);
        #pragma unroll
        for (int ks = 0; ks < 4; ks++) {
            ldsm4(qfh[ks][0], qfh[ks][1], qfh[ks][2], qfh[ks][3], sbQh + qb + ks*32);
            ldsm4(qfl[ks][0], qfl[ks][1], qfl[ks][2], qfl[ks][3], sbQl + qb + ks*32);
        }
    }

    float O[8][4];
    #pragma unroll
    for (int ni = 0; ni < 8; ni++)
        #pragma unroll
        for (int c = 0; c < 4; c++) O[ni][c] = 0.f;
    float m_[2] = {-1e30f, -1e30f}, l_[2] = {0.f, 0.f};

    const int ceil_sv = (S_V + 63) >> 6;
    int kv_lo = 0, kv_hi = 0;
    if (hc == 0)      { if (q0 < S_V) { kv_lo = 0; kv_hi = ceil_sv; } }
    else if (hc == 1) { if (q0 + 63 >= S_V) { kv_lo = S_V >> 6; kv_hi = qt + 1; } }
    else              { kv_lo = 0; kv_hi = (qt + 1 > ceil_sv) ? (qt + 1) : ceil_sv; }

    const int qg = q0 + w*16 + g;
    const uint32_t kvb = (uint32_t)((lrowB*APITCH + lcolB)*2);

    for (int kvt = kv_lo; kvt < kv_hi; kvt++) {
        const int kv0 = kvt * 64;
        __syncthreads();
        {
            int r = tid >> 1, hf = tid & 1;
            int kv = kv0 + r;
            uint4 z = make_uint4(0,0,0,0);
            const uint4* kh_ = (const uint4*)&g_kh[(bh*NT + (kv < NT ? kv : 0))*ND + hf*32];
            const uint4* kl_ = (const uint4*)&g_kl[(bh*NT + (kv < NT ? kv : 0))*ND + hf*32];
            const uint4* vh_ = (const uint4*)&g_vth[(bh*ND + r)*VTP + kv0 + hf*32];
            const uint4* vl_ = (const uint4*)&g_vtl[(bh*ND + r)*VTP + kv0 + hf*32];
            #pragma unroll
            for (int i = 0; i < 4; i++) {
                uint4 a = (kv < NT) ? kh_[i] : z;
                uint4 c = (kv < NT) ? kl_[i] : z;
                *(uint4*)&sKh[r*APITCH + hf*32 + i*8] = a;
                *(uint4*)&sKl[r*APITCH + hf*32 + i*8] = c;
                uint4 d0 = vh_[i];
                uint4 d1 = vl_[i];
                *(uint4*)&sVh[r*APITCH + hf*32 + i*8] = d0;
                *(uint4*)&sVl[r*APITCH + hf*32 + i*8] = d1;
            }
        }
        __syncthreads();

        // ---- S = Q K^T (3-pass split) ----
        float sa[8][4];
        #pragma unroll
        for (int ni = 0; ni < 8; ni++)
            #pragma unroll
            for (int c = 0; c < 4; c++) sa[ni][c] = 0.f;

        #pragma unroll
        for (int ks = 0; ks < 4; ks++) {
            uint32_t bhf[8][2], blf[8][2];
            #pragma unroll
            for (int np = 0; np < 4; np++) {
                ldsm4(bhf[2*np][0], bhf[2*np][1], bhf[2*np+1][0], bhf[2*np+1][1],
                      sbKh + kvb + (uint32_t)(np*16*APITCH*2) + ks*32);
                ldsm4(blf[2*np][0], blf[2*np][1], blf[2*np+1][0], blf[2*np+1][1],
                      sbKl + kvb + (uint32_t)(np*16*APITCH*2) + ks*32);
            }
            #pragma unroll
            for (int ni = 0; ni < 8; ni++)
                mma16(sa[ni], qfh[ks][0], qfh[ks][1], qfh[ks][2], qfh[ks][3],
                      bhf[ni][0], bhf[ni][1]);
            #pragma unroll
            for (int ni = 0; ni < 8; ni++)
                mma16(sa[ni], qfl[ks][0], qfl[ks][1], qfl[ks][2], qfl[ks][3],
                      bhf[ni][0], bhf[ni][1]);
            #pragma unroll
            for (int ni = 0; ni < 8; ni++)
                mma16(sa[ni], qfh[ks][0], qfh[ks][1], qfh[ks][2], qfh[ks][3],
                      blf[ni][0], blf[ni][1]);
        }

        // ---- mask + scale ----
        #pragma unroll
        for (int ni = 0; ni < 8; ni++) {
            #pragma unroll
            for (int c = 0; c < 4; c++) {
                const int qq = qg + ((c >= 2) ? 8 : 0);
                const int kv = kv0 + ni*8 + 2*t + (c & 1);
                bool ok;
                if (hc == 0)      ok = (qq < S_V) && (kv < S_V);
                else if (hc == 1) ok = (qq >= S_V) && (kv >= S_V) && (qq >= kv);
                else              ok = (kv < S_V) || (qq >= kv);
                ok = ok && (kv < NT) && (qq < NT);
                sa[ni][c] = ok ? sa[ni][c] * 0.125f : -1e30f;
            }
        }

        // ---- online softmax ----
        #pragma unroll
        for (int row = 0; row < 2; row++) {
            float rm = -1e30f;
            #pragma unroll
            for (int ni = 0; ni < 8; ni++)
                rm = fmaxf(rm, fmaxf(sa[ni][row*2], sa[ni][row*2+1]));
            rm = fmaxf(rm, __shfl_xor_sync(0xffffffffu, rm, 1));
            rm = fmaxf(rm, __shfl_xor_sync(0xffffffffu, rm, 2));
            float mnew = fmaxf(m_[row], rm);
            float alpha = __expf(m_[row] - mnew);
            m_[row] = mnew;
            float psum = 0.f;
            #pragma unroll
            for (int ni = 0; ni < 8; ni++) {
                float p0 = __expf(sa[ni][row*2]   - mnew);
                float p1 = __expf(sa[ni][row*2+1] - mnew);
                sa[ni][row*2]   = p0;
                sa[ni][row*2+1] = p1;
                psum += p0 + p1;
            }
            psum += __shfl_xor_sync(0xffffffffu, psum, 1);
            psum += __shfl_xor_sync(0xffffffffu, psum, 2);
            l_[row] = l_[row]*alpha + psum;
            #pragma unroll
            for (int ni = 0; ni < 8; ni++) {
                O[ni][row*2]   *= alpha;
                O[ni][row*2+1] *= alpha;
            }
        }

        // ---- P -> A fragments (hi/lo) in registers ----
        uint32_t pfh[4][4], pfl[4][4];
        #pragma unroll
        for (int j = 0; j < 4; j++) {
            __nv_bfloat16 h0, l0, h1, l1;
            bf_split(sa[2*j][0], h0, l0); bf_split(sa[2*j][1], h1, l1);
            pfh[j][0] = us2(h0, h1); pfl[j][0] = us2(l0, l1);
            bf_split(sa[2*j][2], h0, l0); bf_split(sa[2*j][3], h1, l1);
            pfh[j][1] = us2(h0, h1); pfl[j][1] = us2(l0, l1);
            bf_split(sa[2*j+1][0], h0, l0); bf_split(sa[2*j+1][1], h1, l1);
            pfh[j][2] = us2(h0, h1); pfl[j][2] = us2(l0, l1);
            bf_split(sa[2*j+1][2], h0, l0); bf_split(sa[2*j+1][3], h1, l1);
            pfh[j][3] = us2(h0, h1); pfl[j][3] = us2(l0, l1);
        }

        // ---- O += P V (3-pass split) ----
        #pragma unroll
        for (int j = 0; j < 4; j++) {
            uint32_t vhf[8][2], vlf[8][2];
            #pragma unroll
            for (int np = 0; np < 4; np++) {
                ldsm4(vhf[2*np][0], vhf[2*np][1], vhf[2*np+1][0], vhf[2*np+1][1],
                      sbVh + kvb + (uint32_t)(np*16*APITCH*2) + j*32);
                ldsm4(vlf[2*np][0], vlf[2*np][1], vlf[2*np+1][0], vlf[2*np+1][1],
                      sbVl + kvb + (uint32_t)(np*16*APITCH*2) + j*32);
            }
            #pragma unroll
            for (int ni = 0; ni < 8; ni++)
                mma16(O[ni], pfh[j][0], pfh[j][1], pfh[j][2], pfh[j][3],
                      vhf[ni][0], vhf[ni][1]);
            #pragma unroll
            for (int ni = 0; ni < 8; ni++)
                mma16(O[ni], pfl[j][0], pfl[j][1], pfl[j][2], pfl[j][3],
                      vhf[ni][0], vhf[ni][1]);
            #pragma unroll
            for (int ni = 0; ni < 8; ni++)
                mma16(O[ni], pfh[j][0], pfh[j][1], pfh[j][2], pfh[j][3],
                      vlf[ni][0], vlf[ni][1]);
        }
    }

    // ---- epilogue: normalize + write bf16 hi/lo (A operand for proj) ----
    #pragma unroll
    for (int row = 0; row < 2; row++) {
        const int q = q0 + w*16 + g + row*8;
        if (q >= NT) continue;
        const float invl = (m_[row] > -5e29f) ? (1.f / l_[row]) : 0.f;
        const size_t base = ((size_t)(b*NT) + q)*NC + h*ND;
        #pragma unroll
        for (int ni = 0; ni < 8; ni++) {
            float x0 = O[ni][row*2]   * invl;
            float x1 = O[ni][row*2+1] * invl;
            __nv_bfloat16 h0, l0, h1, l1;
            bf_split(x0, h0, l0);
            bf_split(x1, h1, l1);
            *(uint32_t*)&g_xh[base + ni*8 + 2*t] = us2(h0, h1);
            *(uint32_t*)&g_xl[base + ni*8 + 2*t] = us2(l0, l1);
        }
    }
}

// ---------------- launch -----------------------------------------------------
extern "C" void kernel_launch(void* const* d_in, const int* in_sizes, int n_in,
                              void* d_out, int out_size) {
    const float* x  = (const float*)d_in[0];
    const float* Wq = (const float*)d_in[1];
    const float* Wk = (const float*)d_in[2];
    const float* Wv = (const float*)d_in[3];
    const float* Wo = (const float*)d_in[4];
    const float* bo = (const float*)d_in[5];
    const int*   sv = (const int*)d_in[6];
    float* out = (float*)d_out;

    cudaFuncSetAttribute((const void*)qkv_kernel,
                         cudaFuncAttributeMaxDynamicSharedMemorySize, SMEM_GEMM);
    cudaFuncSetAttribute((const void*)proj_kernel,
                         cudaFuncAttributeMaxDynamicSharedMemorySize, SMEM_GEMM);
    cudaFuncSetAttribute((const void*)attn_kernel,
                         cudaFuncAttributeMaxDynamicSharedMemorySize, SMEM_ATTN);

    cis_kernel<<<(NT*32 + 255)/256, 256>>>();

    const int cvt_bx = (NM*NC/4 + 255)/256;
    cvt_kernel<<<dim3(cvt_bx, 5), 256>>>(x, Wq, Wk, Wv, Wo);

    qkv_kernel<<<dim3(NC/BN, (NM + BM - 1)/BM, 3), 128, SMEM_GEMM>>>();
    attn_kernel<<<dim3((NT + 63)/64, NH, NB), 128, SMEM_ATTN>>>(sv);
    proj_kernel<<<dim3(NC/BN, (NM + BM - 1)/BM), 128, SMEM_GEMM>>>(bo, out);
}